// round 1
// baseline (speedup 1.0000x reference)
#include <cuda_runtime.h>
#include <cstdint>
#include <cstdio>

#define D 768
#define DD (768*768)
#define M_ROWS (32*512)
#define L_LAYERS 12

// ---------------- scratch (device globals; no allocation allowed) ----------------
__device__ float g_Wqa[L_LAYERS*DD];
__device__ float g_Wva[L_LAYERS*DD];
__device__ float g_Lf[24*6144];
__device__ float g_Rf[24*6144];
__device__ float g_q[M_ROWS*D];
__device__ float g_k[M_ROWS*D];
__device__ float g_v[M_ROWS*D];
__device__ float g_ctx[M_ROWS*D];
__device__ float g_x[M_ROWS*D];
__device__ int   g_expert;

// ---------------- router: argmax of last sample's logits ----------------
__global__ void router_kernel(const float* __restrict__ hs, const float* __restrict__ rw)
{
    __shared__ float pooled[768];
    __shared__ float logits[8];
    int tid = threadIdx.x;              // 768 threads
    const float* base = hs + (size_t)31 * 512 * 768;
    float s = 0.f;
    for (int i = 0; i < 512; i++) s += base[(size_t)i * 768 + tid];
    pooled[tid] = s * (1.0f / 512.0f);
    __syncthreads();
    int w = tid >> 5, lane = tid & 31;
    if (w < 8) {
        float p = 0.f;
        for (int d = lane; d < 768; d += 32) p += pooled[d] * rw[d * 8 + w];
        #pragma unroll
        for (int o = 16; o; o >>= 1) p += __shfl_xor_sync(0xffffffffu, p, o);
        if (lane == 0) logits[w] = p;
    }
    __syncthreads();
    if (tid == 0) {
        int best = 0; float bv = logits[0];
        for (int e = 1; e < 8; e++) if (logits[e] > bv) { bv = logits[e]; best = e; }
        g_expert = best;
    }
}

// ---------------- TT factors: Lf[768,8] and Rf[8,768] per (layer, weight) ----------------
__global__ void tt_lr_kernel(
    const float* __restrict__ qc0, const float* __restrict__ qc1, const float* __restrict__ qc2,
    const float* __restrict__ qc3, const float* __restrict__ qc4, const float* __restrict__ qc5,
    const float* __restrict__ vc0, const float* __restrict__ vc1, const float* __restrict__ vc2,
    const float* __restrict__ vc3, const float* __restrict__ vc4, const float* __restrict__ vc5)
{
    int l = blockIdx.x, w = blockIdx.y;
    int tid = threadIdx.x;              // 256
    int e = g_expert;
    const float* c0p = (w ? vc0 : qc0) + (size_t)(e * 12 + l) * 96;
    const float* c1p = (w ? vc1 : qc1) + (size_t)(e * 12 + l) * 512;
    const float* c2p = (w ? vc2 : qc2) + (size_t)(e * 12 + l) * 512;
    const float* c3p = (w ? vc3 : qc3) + (size_t)(e * 12 + l) * 512;
    const float* c4p = (w ? vc4 : qc4) + (size_t)(e * 12 + l) * 512;
    const float* c5p = (w ? vc5 : qc5) + (size_t)(e * 12 + l) * 96;

    __shared__ float c0[96], c1[512], c2[512], c3[512], c4[512], c5[96];
    __shared__ float T2[768];
    __shared__ float U2[4096];
    for (int i = tid; i < 96; i += 256) { c0[i] = c0p[i]; c5[i] = c5p[i]; }
    for (int i = tid; i < 512; i += 256) {
        c1[i] = c1p[i]; c2[i] = c2p[i]; c3[i] = c3p[i]; c4[i] = c4p[i];
    }
    __syncthreads();

    // T2[j,l2,m] = sum_k c0[j,k] c1[k,l2,m]   (768 elems)
    for (int t = tid; t < 768; t += 256) {
        int j = t >> 6, l2 = (t >> 3) & 7, m = t & 7;
        float s = 0.f;
        #pragma unroll
        for (int k = 0; k < 8; k++) s += c0[j * 8 + k] * c1[((k * 8 + l2) << 3) + m];
        T2[t] = s;
    }
    // U2[o,p,r,s] = sum_q c3[o,p,q] c4[q,r,s]  (4096 elems)
    for (int t = tid; t < 4096; t += 256) {
        int o = t >> 9, p = (t >> 6) & 7, r = (t >> 3) & 7, ss = t & 7;
        float s = 0.f;
        #pragma unroll
        for (int q = 0; q < 8; q++) s += c3[((o * 8 + p) << 3) + q] * c4[((q * 8 + r) << 3) + ss];
        U2[t] = s;
    }
    __syncthreads();

    int chain = w * 12 + l;
    float* lf = g_Lf + (size_t)chain * 6144;
    float* rf = g_Rf + (size_t)chain * 6144;
    // Lf[row=(j,l2,n), o] = sum_m T2[j,l2,m] c2[m,n,o]
    for (int t = tid; t < 6144; t += 256) {
        int row = t >> 3, o = t & 7;
        int jl = row >> 3, n = row & 7;
        float s = 0.f;
        #pragma unroll
        for (int m = 0; m < 8; m++) s += T2[(jl << 3) + m] * c2[((m * 8 + n) << 3) + o];
        lf[t] = s;
    }
    // Rf[o, col=(p,r,t)] = sum_s U2[o,p,r,s] c5[s,t]
    for (int t = tid; t < 6144; t += 256) {
        int o = t / 768, col = t - o * 768;
        int p = col / 96; int rem = col - p * 96; int r = rem / 12; int tt = rem - r * 12;
        float s = 0.f;
        #pragma unroll
        for (int ss = 0; ss < 8; ss++) s += U2[(((o * 8 + p) << 3) + r) * 8 + ss] * c5[ss * 12 + tt];
        rf[t] = s;
    }
}

// ---------------- W_a = W + 8 * Lf·Rf ----------------
__global__ void tt_build_kernel(const float* __restrict__ Wq, const float* __restrict__ Wv)
{
    int l = blockIdx.y, w = blockIdx.z;
    int t = blockIdx.x * 256 + threadIdx.x;      // < 589824
    int row = t / 768, col = t - row * 768;
    int chain = w * 12 + l;
    const float* lf = g_Lf + (size_t)chain * 6144 + row * 8;
    const float* rf = g_Rf + (size_t)chain * 6144 + col;
    float s = 0.f;
    #pragma unroll
    for (int o = 0; o < 8; o++) s += lf[o] * rf[o * 768];
    const float* W = w ? Wv : Wq;
    float* Wo_ = w ? g_Wva : g_Wqa;
    size_t idx = (size_t)l * DD + t;
    Wo_[idx] = W[idx] + 8.0f * s;
}

// ---------------- SGEMM 128x128x8: O = A @ W^T + bias (W row-major [N,K]) ----------------
__global__ __launch_bounds__(256) void sgemm_bias(
    const float* __restrict__ A,
    const float* __restrict__ W0, const float* __restrict__ W1, const float* __restrict__ W2,
    const float* __restrict__ b0, const float* __restrict__ b1, const float* __restrict__ b2,
    float* __restrict__ O0, float* __restrict__ O1, float* __restrict__ O2)
{
    const float* W    = blockIdx.z == 0 ? W0 : (blockIdx.z == 1 ? W1 : W2);
    const float* bias = blockIdx.z == 0 ? b0 : (blockIdx.z == 1 ? b1 : b2);
    float*       O    = blockIdx.z == 0 ? O0 : (blockIdx.z == 1 ? O1 : O2);

    __shared__ __align__(16) float As[8][128];
    __shared__ __align__(16) float Bs[8][128];
    int tid = threadIdx.x;
    int bm = blockIdx.y * 128, bn = blockIdx.x * 128;
    int lrow = tid >> 1;
    int lc4 = (tid & 1) * 4;
    const float* Ag = A + (size_t)(bm + lrow) * D + lc4;
    const float* Wg = W + (size_t)(bn + lrow) * D + lc4;
    int ty = tid >> 4, tx = tid & 15;

    float acc[8][8];
    #pragma unroll
    for (int i = 0; i < 8; i++)
        #pragma unroll
        for (int j = 0; j < 8; j++) acc[i][j] = 0.f;

    for (int kt = 0; kt < D; kt += 8) {
        float4 av = *(const float4*)(Ag + kt);
        float4 wv = *(const float4*)(Wg + kt);
        As[lc4 + 0][lrow] = av.x; As[lc4 + 1][lrow] = av.y;
        As[lc4 + 2][lrow] = av.z; As[lc4 + 3][lrow] = av.w;
        Bs[lc4 + 0][lrow] = wv.x; Bs[lc4 + 1][lrow] = wv.y;
        Bs[lc4 + 2][lrow] = wv.z; Bs[lc4 + 3][lrow] = wv.w;
        __syncthreads();
        #pragma unroll
        for (int kk = 0; kk < 8; kk++) {
            float a[8], b[8];
            *(float4*)&a[0] = *(const float4*)&As[kk][ty * 8];
            *(float4*)&a[4] = *(const float4*)&As[kk][ty * 8 + 4];
            *(float4*)&b[0] = *(const float4*)&Bs[kk][tx * 8];
            *(float4*)&b[4] = *(const float4*)&Bs[kk][tx * 8 + 4];
            #pragma unroll
            for (int i = 0; i < 8; i++)
                #pragma unroll
                for (int j = 0; j < 8; j++) acc[i][j] = fmaf(a[i], b[j], acc[i][j]);
        }
        __syncthreads();
    }
    float bb[8];
    #pragma unroll
    for (int j = 0; j < 8; j++) bb[j] = bias[bn + tx * 8 + j];
    #pragma unroll
    for (int i = 0; i < 8; i++) {
        int row = bm + ty * 8 + i;
        float* orow = O + (size_t)row * D + bn + tx * 8;
        float4 o0, o1;
        o0.x = acc[i][0] + bb[0]; o0.y = acc[i][1] + bb[1];
        o0.z = acc[i][2] + bb[2]; o0.w = acc[i][3] + bb[3];
        o1.x = acc[i][4] + bb[4]; o1.y = acc[i][5] + bb[5];
        o1.z = acc[i][6] + bb[6]; o1.w = acc[i][7] + bb[7];
        *(float4*)orow = o0;
        *(float4*)(orow + 4) = o1;
    }
}

// ---------------- fused attention (flash style, 64-query tiles) ----------------
// grid (8 qtiles, 12 heads, 32 batch), 256 threads, dynamic smem
#define ATT_STRIDE 68
#define ATT_SMEM_FLOATS (3 * 64 * ATT_STRIDE + 192)
__global__ __launch_bounds__(256) void attn_kernel(
    const float* __restrict__ Q, const float* __restrict__ K,
    const float* __restrict__ V, float* __restrict__ Oc)
{
    extern __shared__ float sm[];
    float* Qs  = sm;                        // [d][q]  stride 68
    float* KVs = sm + 64 * ATT_STRIDE;      // K: [d][k] then V: [k][d]
    float* Ss  = sm + 2 * 64 * ATT_STRIDE;  // [q][k]  stride 68
    float* mrow = sm + 3 * 64 * ATT_STRIDE;
    float* lrow = mrow + 64;
    float* arow = lrow + 64;

    int tid = threadIdx.x;
    int qt = blockIdx.x, h = blockIdx.y, b = blockIdx.z;
    size_t headoff = (size_t)b * 512 * 768 + (size_t)h * 64;
    int ty = tid >> 4, tx = tid & 15;

    // load Q transposed, pre-scaled by 1/sqrt(64)
    #pragma unroll
    for (int i = 0; i < 16; i++) {
        int idx = tid + i * 256;
        int sl = idx >> 6, d = idx & 63;
        Qs[d * ATT_STRIDE + sl] = Q[headoff + (size_t)(qt * 64 + sl) * 768 + d] * 0.125f;
    }
    if (tid < 64) { mrow[tid] = -1e30f; lrow[tid] = 0.f; }
    float acc[4][4];
    #pragma unroll
    for (int i = 0; i < 4; i++)
        #pragma unroll
        for (int j = 0; j < 4; j++) acc[i][j] = 0.f;
    __syncthreads();

    for (int kt = 0; kt < 8; kt++) {
        // K tile, transposed [d][k]
        #pragma unroll
        for (int i = 0; i < 16; i++) {
            int idx = tid + i * 256;
            int sl = idx >> 6, d = idx & 63;
            KVs[d * ATT_STRIDE + sl] = K[headoff + (size_t)(kt * 64 + sl) * 768 + d];
        }
        __syncthreads();

        float s[4][4];
        #pragma unroll
        for (int i = 0; i < 4; i++)
            #pragma unroll
            for (int j = 0; j < 4; j++) s[i][j] = 0.f;
        #pragma unroll 8
        for (int kk = 0; kk < 64; kk++) {
            float4 qv = *(const float4*)&Qs[kk * ATT_STRIDE + ty * 4];
            float4 kv = *(const float4*)&KVs[kk * ATT_STRIDE + tx * 4];
            float qa[4] = {qv.x, qv.y, qv.z, qv.w};
            float ka[4] = {kv.x, kv.y, kv.z, kv.w};
            #pragma unroll
            for (int i = 0; i < 4; i++)
                #pragma unroll
                for (int j = 0; j < 4; j++) s[i][j] = fmaf(qa[i], ka[j], s[i][j]);
        }
        #pragma unroll
        for (int i = 0; i < 4; i++) {
            float4 sv = make_float4(s[i][0], s[i][1], s[i][2], s[i][3]);
            *(float4*)&Ss[(ty * 4 + i) * ATT_STRIDE + tx * 4] = sv;
        }
        __syncthreads();   // S ready; K reads done

        // V tile natural [k][d] (reuse K buffer)
        #pragma unroll
        for (int i = 0; i < 16; i++) {
            int idx = tid + i * 256;
            int sl = idx >> 6, d = idx & 63;
            KVs[sl * ATT_STRIDE + d] = V[headoff + (size_t)(kt * 64 + sl) * 768 + d];
        }
        // online softmax per query row
        if (tid < 64) {
            int r = tid;
            float* srow = Ss + r * ATT_STRIDE;
            float mold = mrow[r];
            float mx = mold;
            #pragma unroll 8
            for (int j = 0; j < 64; j++) mx = fmaxf(mx, srow[j]);
            float sum = 0.f;
            #pragma unroll 8
            for (int j = 0; j < 64; j++) { float p = __expf(srow[j] - mx); srow[j] = p; sum += p; }
            float al = __expf(mold - mx);
            lrow[r] = lrow[r] * al + sum;
            mrow[r] = mx;
            arow[r] = al;
        }
        __syncthreads();

        float al[4];
        #pragma unroll
        for (int i = 0; i < 4; i++) al[i] = arow[ty * 4 + i];
        #pragma unroll
        for (int i = 0; i < 4; i++)
            #pragma unroll
            for (int j = 0; j < 4; j++) acc[i][j] *= al[i];
        #pragma unroll 8
        for (int kk = 0; kk < 64; kk++) {
            float p[4];
            #pragma unroll
            for (int i = 0; i < 4; i++) p[i] = Ss[(ty * 4 + i) * ATT_STRIDE + kk];
            float4 vv = *(const float4*)&KVs[kk * ATT_STRIDE + tx * 4];
            float va[4] = {vv.x, vv.y, vv.z, vv.w};
            #pragma unroll
            for (int i = 0; i < 4; i++)
                #pragma unroll
                for (int j = 0; j < 4; j++) acc[i][j] = fmaf(p[i], va[j], acc[i][j]);
        }
        __syncthreads();   // before next tile overwrites KVs/Ss
    }

    float inv[4];
    #pragma unroll
    for (int i = 0; i < 4; i++) inv[i] = 1.f / lrow[ty * 4 + i];
    #pragma unroll
    for (int i = 0; i < 4; i++) {
        int row = qt * 64 + ty * 4 + i;
        float* orow = Oc + headoff + (size_t)row * 768 + tx * 4;
        float4 o;
        o.x = acc[i][0] * inv[i]; o.y = acc[i][1] * inv[i];
        o.z = acc[i][2] * inv[i]; o.w = acc[i][3] * inv[i];
        *(float4*)orow = o;
    }
}

// ---------------- residual + layernorm ----------------
__device__ __forceinline__ float block_sum256(float v, float* red)
{
    #pragma unroll
    for (int o = 16; o; o >>= 1) v += __shfl_xor_sync(0xffffffffu, v, o);
    int w = threadIdx.x >> 5;
    if ((threadIdx.x & 31) == 0) red[w] = v;
    __syncthreads();
    if (threadIdx.x < 8) {
        v = red[threadIdx.x];
        #pragma unroll
        for (int o = 4; o; o >>= 1) v += __shfl_xor_sync(0xffu, v, o);
        if (threadIdx.x == 0) red[0] = v;
    }
    __syncthreads();
    float r = red[0];
    __syncthreads();
    return r;
}

__global__ __launch_bounds__(256) void ln_kernel(
    const float* __restrict__ x, const float* __restrict__ o,
    const float* __restrict__ sc, const float* __restrict__ bi,
    float* __restrict__ out)
{
    __shared__ float red[8];
    size_t base = (size_t)blockIdx.x * 768;
    int tid = threadIdx.x;
    float v[3];
    #pragma unroll
    for (int i = 0; i < 3; i++) {
        int d = tid + i * 256;
        v[i] = x[base + d] + o[base + d];
    }
    float mu = block_sum256(v[0] + v[1] + v[2], red) * (1.0f / 768.0f);
    float d0 = v[0] - mu, d1 = v[1] - mu, d2 = v[2] - mu;
    float var = block_sum256(d0 * d0 + d1 * d1 + d2 * d2, red) * (1.0f / 768.0f);
    float rstd = rsqrtf(var + 1e-12f);
    #pragma unroll
    for (int i = 0; i < 3; i++) {
        int d = tid + i * 256;
        out[base + d] = (v[i] - mu) * rstd * sc[d] + bi[d];
    }
}

// ---------------- launch ----------------
extern "C" void kernel_launch(void* const* d_in, const int* in_sizes, int n_in,
                              void* d_out, int out_size)
{
    (void)in_sizes; (void)n_in; (void)out_size;
    const float* hs  = (const float*)d_in[0];
    const float* rw  = (const float*)d_in[1];
    const float* qc[6], * vc[6];
    for (int i = 0; i < 6; i++) { qc[i] = (const float*)d_in[2 + i]; vc[i] = (const float*)d_in[8 + i]; }
    const float* Wq = (const float*)d_in[14];
    const float* Wk = (const float*)d_in[15];
    const float* Wv = (const float*)d_in[16];
    const float* Wo = (const float*)d_in[17];
    const float* bq = (const float*)d_in[18];
    const float* bk = (const float*)d_in[19];
    const float* bv = (const float*)d_in[20];
    const float* bo = (const float*)d_in[21];
    const float* lns = (const float*)d_in[22];
    const float* lnb = (const float*)d_in[23];

    float *Wqa, *Wva, *q, *k, *v, *ctx, *x;
    cudaGetSymbolAddress((void**)&Wqa, g_Wqa);
    cudaGetSymbolAddress((void**)&Wva, g_Wva);
    cudaGetSymbolAddress((void**)&q,   g_q);
    cudaGetSymbolAddress((void**)&k,   g_k);
    cudaGetSymbolAddress((void**)&v,   g_v);
    cudaGetSymbolAddress((void**)&ctx, g_ctx);
    cudaGetSymbolAddress((void**)&x,   g_x);

    const int ATT_SMEM = ATT_SMEM_FLOATS * 4;
    cudaFuncSetAttribute(attn_kernel, cudaFuncAttributeMaxDynamicSharedMemorySize, ATT_SMEM);

    router_kernel<<<1, 768>>>(hs, rw);
    tt_lr_kernel<<<dim3(12, 2), 256>>>(qc[0], qc[1], qc[2], qc[3], qc[4], qc[5],
                                       vc[0], vc[1], vc[2], vc[3], vc[4], vc[5]);
    tt_build_kernel<<<dim3(DD / 256, 12, 2), 256>>>(Wq, Wv);

    for (int l = 0; l < 12; l++) {
        const float* xin = l ? (const float*)x : hs;
        float* xout = (l == 11) ? (float*)d_out : x;
        size_t wo = (size_t)l * DD;
        size_t bo_off = (size_t)l * D;
        sgemm_bias<<<dim3(6, 128, 3), 256>>>(xin,
            Wqa + wo, Wk + wo, Wva + wo,
            bq + bo_off, bk + bo_off, bv + bo_off,
            q, k, v);
        attn_kernel<<<dim3(8, 12, 32), 256, ATT_SMEM>>>(q, k, v, ctx);
        // output projection -> reuse g_k as scratch
        sgemm_bias<<<dim3(6, 128, 1), 256>>>(ctx,
            Wo + wo, Wo + wo, Wo + wo,
            bo + bo_off, bo + bo_off, bo + bo_off,
            k, k, k);
        ln_kernel<<<16384, 256>>>(xin, k, lns + bo_off, lnb + bo_off, xout);
    }
}

// round 2
// speedup vs baseline: 2.4296x; 2.4296x over previous
#include <cuda_runtime.h>
#include <cuda_bf16.h>
#include <cstdint>

#define D 768
#define DD (768*768)
#define M_ROWS (32*512)
#define L_LAYERS 12
#define NW (L_LAYERS*DD)

typedef __nv_bfloat16 bf16;

// ---------------- scratch (device globals; no allocation allowed) ----------------
__device__ float g_x[M_ROWS*D];
__device__ float g_o[M_ROWS*D];
__device__ bf16 g_xh[M_ROWS*D], g_xl[M_ROWS*D];
__device__ bf16 g_qh[M_ROWS*D], g_ql[M_ROWS*D];
__device__ bf16 g_kh[M_ROWS*D], g_kl[M_ROWS*D];
__device__ bf16 g_vh[M_ROWS*D], g_vl[M_ROWS*D];
__device__ bf16 g_ch[M_ROWS*D], g_cl[M_ROWS*D];
__device__ bf16 g_Wqa_h[NW], g_Wqa_l[NW], g_Wva_h[NW], g_Wva_l[NW];
__device__ bf16 g_Wk_h[NW],  g_Wk_l[NW],  g_Wo_h[NW],  g_Wo_l[NW];
__device__ float g_Lf[24*6144], g_Rf[24*6144];
__device__ int   g_expert;

// ---------------- small helpers ----------------
__device__ __forceinline__ void split_pair(float v0, float v1, uint32_t& hi, uint32_t& lo)
{
    bf16 h0 = __float2bfloat16(v0), h1 = __float2bfloat16(v1);
    float r0 = v0 - __bfloat162float(h0), r1 = v1 - __bfloat162float(h1);
    __nv_bfloat162 H; H.x = h0; H.y = h1;
    __nv_bfloat162 L = __floats2bfloat162_rn(r0, r1);
    hi = *reinterpret_cast<uint32_t*>(&H);
    lo = *reinterpret_cast<uint32_t*>(&L);
}

__device__ __forceinline__ void ldm_x4(uint32_t* r, const bf16* p)
{
    uint32_t a = (uint32_t)__cvta_generic_to_shared(p);
    asm volatile("ldmatrix.sync.aligned.m8n8.x4.shared.b16 {%0,%1,%2,%3}, [%4];"
        : "=r"(r[0]), "=r"(r[1]), "=r"(r[2]), "=r"(r[3]) : "r"(a));
}
__device__ __forceinline__ void ldm_x4_t(uint32_t* r, const bf16* p)
{
    uint32_t a = (uint32_t)__cvta_generic_to_shared(p);
    asm volatile("ldmatrix.sync.aligned.m8n8.x4.trans.shared.b16 {%0,%1,%2,%3}, [%4];"
        : "=r"(r[0]), "=r"(r[1]), "=r"(r[2]), "=r"(r[3]) : "r"(a));
}
__device__ __forceinline__ void mma16816(float* d, const uint32_t* a, uint32_t b0, uint32_t b1)
{
    asm volatile("mma.sync.aligned.m16n8k16.row.col.f32.bf16.bf16.f32 "
        "{%0,%1,%2,%3}, {%4,%5,%6,%7}, {%8,%9}, {%0,%1,%2,%3};"
        : "+f"(d[0]), "+f"(d[1]), "+f"(d[2]), "+f"(d[3])
        : "r"(a[0]), "r"(a[1]), "r"(a[2]), "r"(a[3]), "r"(b0), "r"(b1));
}
__device__ __forceinline__ void cp16(const bf16* smem_dst, const bf16* gsrc)
{
    uint32_t s = (uint32_t)__cvta_generic_to_shared(smem_dst);
    asm volatile("cp.async.cg.shared.global [%0], [%1], 16;" :: "r"(s), "l"(gsrc));
}

// ---------------- router ----------------
__global__ void router_kernel(const float* __restrict__ hs, const float* __restrict__ rw)
{
    __shared__ float pooled[768];
    __shared__ float logits[8];
    int tid = threadIdx.x;
    const float* base = hs + (size_t)31 * 512 * 768;
    float s = 0.f;
    for (int i = 0; i < 512; i++) s += base[(size_t)i * 768 + tid];
    pooled[tid] = s * (1.0f / 512.0f);
    __syncthreads();
    int w = tid >> 5, lane = tid & 31;
    if (w < 8) {
        float p = 0.f;
        for (int d = lane; d < 768; d += 32) p += pooled[d] * rw[d * 8 + w];
        #pragma unroll
        for (int o = 16; o; o >>= 1) p += __shfl_xor_sync(0xffffffffu, p, o);
        if (lane == 0) logits[w] = p;
    }
    __syncthreads();
    if (tid == 0) {
        int best = 0; float bv = logits[0];
        for (int e = 1; e < 8; e++) if (logits[e] > bv) { bv = logits[e]; best = e; }
        g_expert = best;
    }
}

// ---------------- TT factors ----------------
__global__ void tt_lr_kernel(
    const float* __restrict__ qc0, const float* __restrict__ qc1, const float* __restrict__ qc2,
    const float* __restrict__ qc3, const float* __restrict__ qc4, const float* __restrict__ qc5,
    const float* __restrict__ vc0, const float* __restrict__ vc1, const float* __restrict__ vc2,
    const float* __restrict__ vc3, const float* __restrict__ vc4, const float* __restrict__ vc5)
{
    int l = blockIdx.x, w = blockIdx.y;
    int tid = threadIdx.x;
    int e = g_expert;
    const float* c0p = (w ? vc0 : qc0) + (size_t)(e * 12 + l) * 96;
    const float* c1p = (w ? vc1 : qc1) + (size_t)(e * 12 + l) * 512;
    const float* c2p = (w ? vc2 : qc2) + (size_t)(e * 12 + l) * 512;
    const float* c3p = (w ? vc3 : qc3) + (size_t)(e * 12 + l) * 512;
    const float* c4p = (w ? vc4 : qc4) + (size_t)(e * 12 + l) * 512;
    const float* c5p = (w ? vc5 : qc5) + (size_t)(e * 12 + l) * 96;

    __shared__ float c0[96], c1[512], c2[512], c3[512], c4[512], c5[96];
    __shared__ float T2[768];
    __shared__ float U2[4096];
    for (int i = tid; i < 96; i += 256) { c0[i] = c0p[i]; c5[i] = c5p[i]; }
    for (int i = tid; i < 512; i += 256) {
        c1[i] = c1p[i]; c2[i] = c2p[i]; c3[i] = c3p[i]; c4[i] = c4p[i];
    }
    __syncthreads();

    for (int t = tid; t < 768; t += 256) {
        int j = t >> 6, l2 = (t >> 3) & 7, m = t & 7;
        float s = 0.f;
        #pragma unroll
        for (int k = 0; k < 8; k++) s += c0[j * 8 + k] * c1[((k * 8 + l2) << 3) + m];
        T2[t] = s;
    }
    for (int t = tid; t < 4096; t += 256) {
        int o = t >> 9, p = (t >> 6) & 7, r = (t >> 3) & 7, ss = t & 7;
        float s = 0.f;
        #pragma unroll
        for (int q = 0; q < 8; q++) s += c3[((o * 8 + p) << 3) + q] * c4[((q * 8 + r) << 3) + ss];
        U2[t] = s;
    }
    __syncthreads();

    int chain = w * 12 + l;
    float* lf = g_Lf + (size_t)chain * 6144;
    float* rf = g_Rf + (size_t)chain * 6144;
    for (int t = tid; t < 6144; t += 256) {
        int row = t >> 3, o = t & 7;
        int jl = row >> 3, n = row & 7;
        float s = 0.f;
        #pragma unroll
        for (int m = 0; m < 8; m++) s += T2[(jl << 3) + m] * c2[((m * 8 + n) << 3) + o];
        lf[t] = s;
    }
    for (int t = tid; t < 6144; t += 256) {
        int o = t / 768, col = t - o * 768;
        int p = col / 96; int rem = col - p * 96; int r = rem / 12; int tt = rem - r * 12;
        float s = 0.f;
        #pragma unroll
        for (int ss = 0; ss < 8; ss++) s += U2[(((o * 8 + p) << 3) + r) * 8 + ss] * c5[ss * 12 + tt];
        rf[t] = s;
    }
}

// ---------------- W_a = W + 8 * Lf·Rf, emitted as bf16 hi/lo ----------------
__global__ void tt_build_kernel(const float* __restrict__ Wq, const float* __restrict__ Wv)
{
    int l = blockIdx.y, w = blockIdx.z;
    int t = blockIdx.x * 256 + threadIdx.x;
    int row = t / 768, col = t - row * 768;
    int chain = w * 12 + l;
    const float* lf = g_Lf + (size_t)chain * 6144 + row * 8;
    const float* rf = g_Rf + (size_t)chain * 6144 + col;
    float s = 0.f;
    #pragma unroll
    for (int o = 0; o < 8; o++) s += lf[o] * rf[o * 768];
    const float* W = w ? Wv : Wq;
    float val = W[(size_t)l * DD + t] + 8.0f * s;
    bf16* Wh = w ? g_Wva_h : g_Wqa_h;
    bf16* Wl = w ? g_Wva_l : g_Wqa_l;
    size_t idx = (size_t)l * DD + t;
    bf16 h = __float2bfloat16(val);
    Wh[idx] = h;
    Wl[idx] = __float2bfloat16(val - __bfloat162float(h));
}

// ---------------- fp32 -> bf16 hi/lo split ----------------
__global__ void convert_split(const float* __restrict__ s, bf16* __restrict__ h,
                              bf16* __restrict__ l, int n)
{
    int i = blockIdx.x * 256 + threadIdx.x;
    if (i < n) {
        float v = s[i];
        bf16 hh = __float2bfloat16(v);
        h[i] = hh;
        l[i] = __float2bfloat16(v - __bfloat162float(hh));
    }
}

// ---------------- GEMM: O = A @ W^T + bias, bf16-split 3-pass MMA ----------------
// tile 128x128x32, 256 threads (8 warps, 4x2), cp.async double buffered.
// EPI=1: write bf16 hi/lo; EPI=0: write fp32.
template<int EPI>
__global__ __launch_bounds__(256) void gemm_mma(
    const bf16* __restrict__ Ah, const bf16* __restrict__ Al,
    const bf16* __restrict__ W0h, const bf16* __restrict__ W0l,
    const bf16* __restrict__ W1h, const bf16* __restrict__ W1l,
    const bf16* __restrict__ W2h, const bf16* __restrict__ W2l,
    const float* __restrict__ bias0, const float* __restrict__ bias1, const float* __restrict__ bias2,
    void* o0a, void* o0b, void* o1a, void* o1b, void* o2a, void* o2b)
{
    extern __shared__ bf16 sm[];
    bf16* sAh = sm;               // [2][128*40]
    bf16* sAl = sm + 2 * 5120;
    bf16* sBh = sm + 4 * 5120;
    bf16* sBl = sm + 6 * 5120;

    int z = blockIdx.z;
    const bf16* Wh = z == 0 ? W0h : (z == 1 ? W1h : W2h);
    const bf16* Wl = z == 0 ? W0l : (z == 1 ? W1l : W2l);
    const float* bias = z == 0 ? bias0 : (z == 1 ? bias1 : bias2);
    void* Oa = z == 0 ? o0a : (z == 1 ? o1a : o2a);
    void* Ob = z == 0 ? o0b : (z == 1 ? o1b : o2b);

    int tid = threadIdx.x;
    int lane = tid & 31, warp = tid >> 5;
    int wm = warp >> 1, wn = warp & 1;
    int bm = blockIdx.y * 128, bn = blockIdx.x * 128;

    float acc[2][8][4];
    #pragma unroll
    for (int i = 0; i < 2; i++)
        #pragma unroll
        for (int j = 0; j < 8; j++)
            #pragma unroll
            for (int q = 0; q < 4; q++) acc[i][j][q] = 0.f;

    // stage loader: 512 16B-chunks per array, 2 per thread
    #define LOAD_STAGE(KT, S)                                                     \
    {                                                                             \
        _Pragma("unroll")                                                         \
        for (int i_ = 0; i_ < 2; i_++) {                                          \
            int c_ = tid + i_ * 256;                                              \
            int row_ = c_ >> 2, seg_ = (c_ & 3) * 8;                              \
            size_t ga_ = (size_t)(bm + row_) * D + (KT) * 32 + seg_;              \
            size_t gb_ = (size_t)(bn + row_) * D + (KT) * 32 + seg_;              \
            int so_ = (S) * 5120 + row_ * 40 + seg_;                              \
            cp16(sAh + so_, Ah + ga_); cp16(sAl + so_, Al + ga_);                 \
            cp16(sBh + so_, Wh + gb_); cp16(sBl + so_, Wl + gb_);                 \
        }                                                                         \
        asm volatile("cp.async.commit_group;");                                   \
    }

    LOAD_STAGE(0, 0)

    for (int kt = 0; kt < 24; kt++) {
        int s = kt & 1;
        if (kt < 23) {
            LOAD_STAGE(kt + 1, s ^ 1)
            asm volatile("cp.async.wait_group 1;");
        } else {
            asm volatile("cp.async.wait_group 0;");
        }
        __syncthreads();

        #pragma unroll
        for (int kk = 0; kk < 2; kk++) {
            uint32_t afh[2][4], afl[2][4];
            #pragma unroll
            for (int im = 0; im < 2; im++) {
                int r = wm * 32 + im * 16 + (lane & 7) + ((lane >> 3) & 1) * 8;
                int ko = kk * 16 + (lane >> 4) * 8;
                ldm_x4(afh[im], sAh + s * 5120 + r * 40 + ko);
                ldm_x4(afl[im], sAl + s * 5120 + r * 40 + ko);
            }
            #pragma unroll
            for (int j2 = 0; j2 < 4; j2++) {
                int nr = wn * 64 + j2 * 16 + (lane & 7) + (lane >> 4) * 8;
                int ko = kk * 16 + ((lane >> 3) & 1) * 8;
                uint32_t bh[4], bl[4];
                ldm_x4(bh, sBh + s * 5120 + nr * 40 + ko);
                ldm_x4(bl, sBl + s * 5120 + nr * 40 + ko);
                #pragma unroll
                for (int im = 0; im < 2; im++) {
                    mma16816(acc[im][2*j2],   afh[im], bh[0], bh[1]);
                    mma16816(acc[im][2*j2],   afh[im], bl[0], bl[1]);
                    mma16816(acc[im][2*j2],   afl[im], bh[0], bh[1]);
                    mma16816(acc[im][2*j2+1], afh[im], bh[2], bh[3]);
                    mma16816(acc[im][2*j2+1], afh[im], bl[2], bl[3]);
                    mma16816(acc[im][2*j2+1], afl[im], bh[2], bh[3]);
                }
            }
        }
        __syncthreads();
    }

    #pragma unroll
    for (int im = 0; im < 2; im++) {
        int row0 = bm + wm * 32 + im * 16 + (lane >> 2);
        #pragma unroll
        for (int j = 0; j < 8; j++) {
            int col = bn + wn * 64 + j * 8 + (lane & 3) * 2;
            float b0v = bias[col], b1v = bias[col + 1];
            float v00 = acc[im][j][0] + b0v, v01 = acc[im][j][1] + b1v;
            float v10 = acc[im][j][2] + b0v, v11 = acc[im][j][3] + b1v;
            if (EPI == 1) {
                uint32_t h2, l2;
                split_pair(v00, v01, h2, l2);
                *(uint32_t*)((bf16*)Oa + (size_t)row0 * D + col) = h2;
                *(uint32_t*)((bf16*)Ob + (size_t)row0 * D + col) = l2;
                split_pair(v10, v11, h2, l2);
                *(uint32_t*)((bf16*)Oa + (size_t)(row0 + 8) * D + col) = h2;
                *(uint32_t*)((bf16*)Ob + (size_t)(row0 + 8) * D + col) = l2;
            } else {
                float2 f0 = make_float2(v00, v01), f1 = make_float2(v10, v11);
                *(float2*)((float*)Oa + (size_t)row0 * D + col) = f0;
                *(float2*)((float*)Oa + (size_t)(row0 + 8) * D + col) = f1;
            }
        }
    }
}

// ---------------- flash attention, bf16-split 3-pass MMA ----------------
// grid (4 qtiles, 12 heads, 32 batch), 256 threads; warp owns 16 q-rows.
__global__ __launch_bounds__(256) void attn_mma(
    const bf16* __restrict__ Qh, const bf16* __restrict__ Ql,
    const bf16* __restrict__ Kh, const bf16* __restrict__ Kl,
    const bf16* __restrict__ Vh, const bf16* __restrict__ Vl,
    bf16* __restrict__ Ch, bf16* __restrict__ Cl)
{
    __shared__ bf16 KVh[128 * 72], KVl[128 * 72];
    int tid = threadIdx.x, lane = tid & 31, warp = tid >> 5;
    int qt = blockIdx.x, h = blockIdx.y, b = blockIdx.z;
    int rb = b * 512 + qt * 128;
    int chd = h * 64;

    // stage Q
    #pragma unroll
    for (int i = 0; i < 4; i++) {
        int c = tid + i * 256;
        int row = c >> 3, seg = (c & 7) * 8;
        *(uint4*)(KVh + row * 72 + seg) = *(const uint4*)(Qh + (size_t)(rb + row) * D + chd + seg);
        *(uint4*)(KVl + row * 72 + seg) = *(const uint4*)(Ql + (size_t)(rb + row) * D + chd + seg);
    }
    __syncthreads();
    uint32_t qfh[4][4], qfl[4][4];
    #pragma unroll
    for (int kc = 0; kc < 4; kc++) {
        int r = warp * 16 + (lane & 7) + ((lane >> 3) & 1) * 8;
        int ko = kc * 16 + (lane >> 4) * 8;
        ldm_x4(qfh[kc], KVh + r * 72 + ko);
        ldm_x4(qfl[kc], KVl + r * 72 + ko);
    }
    __syncthreads();

    float m0 = -1e30f, m1 = -1e30f, l0 = 0.f, l1 = 0.f;
    float oac[8][4];
    #pragma unroll
    for (int j = 0; j < 8; j++)
        #pragma unroll
        for (int q = 0; q < 4; q++) oac[j][q] = 0.f;

    for (int kt = 0; kt < 4; kt++) {
        // K tile
        #pragma unroll
        for (int i = 0; i < 4; i++) {
            int c = tid + i * 256;
            int row = c >> 3, seg = (c & 7) * 8;
            size_t g = (size_t)(b * 512 + kt * 128 + row) * D + chd + seg;
            *(uint4*)(KVh + row * 72 + seg) = *(const uint4*)(Kh + g);
            *(uint4*)(KVl + row * 72 + seg) = *(const uint4*)(Kl + g);
        }
        __syncthreads();

        float sa[16][4];
        #pragma unroll
        for (int j = 0; j < 16; j++)
            #pragma unroll
            for (int q = 0; q < 4; q++) sa[j][q] = 0.f;

        #pragma unroll
        for (int kc = 0; kc < 4; kc++) {
            #pragma unroll
            for (int j2 = 0; j2 < 8; j2++) {
                int nr = j2 * 16 + (lane & 7) + (lane >> 4) * 8;
                int ko = kc * 16 + ((lane >> 3) & 1) * 8;
                uint32_t bh[4], bl[4];
                ldm_x4(bh, KVh + nr * 72 + ko);
                ldm_x4(bl, KVl + nr * 72 + ko);
                mma16816(sa[2*j2],   qfh[kc], bh[0], bh[1]);
                mma16816(sa[2*j2],   qfh[kc], bl[0], bl[1]);
                mma16816(sa[2*j2],   qfl[kc], bh[0], bh[1]);
                mma16816(sa[2*j2+1], qfh[kc], bh[2], bh[3]);
                mma16816(sa[2*j2+1], qfh[kc], bl[2], bl[3]);
                mma16816(sa[2*j2+1], qfl[kc], bh[2], bh[3]);
            }
        }

        // online softmax (rows g = lane>>2 and g+8; stats replicated across quad)
        float mx0 = -1e30f, mx1 = -1e30f;
        #pragma unroll
        for (int j = 0; j < 16; j++) {
            sa[j][0] *= 0.125f; sa[j][1] *= 0.125f; sa[j][2] *= 0.125f; sa[j][3] *= 0.125f;
            mx0 = fmaxf(mx0, fmaxf(sa[j][0], sa[j][1]));
            mx1 = fmaxf(mx1, fmaxf(sa[j][2], sa[j][3]));
        }
        mx0 = fmaxf(mx0, __shfl_xor_sync(0xffffffffu, mx0, 1));
        mx0 = fmaxf(mx0, __shfl_xor_sync(0xffffffffu, mx0, 2));
        mx1 = fmaxf(mx1, __shfl_xor_sync(0xffffffffu, mx1, 1));
        mx1 = fmaxf(mx1, __shfl_xor_sync(0xffffffffu, mx1, 2));
        float mn0 = fmaxf(m0, mx0), mn1 = fmaxf(m1, mx1);
        float al0 = __expf(m0 - mn0), al1 = __expf(m1 - mn1);
        m0 = mn0; m1 = mn1;
        float s0 = 0.f, s1 = 0.f;
        #pragma unroll
        for (int j = 0; j < 16; j++) {
            sa[j][0] = __expf(sa[j][0] - mn0); sa[j][1] = __expf(sa[j][1] - mn0);
            sa[j][2] = __expf(sa[j][2] - mn1); sa[j][3] = __expf(sa[j][3] - mn1);
            s0 += sa[j][0] + sa[j][1];
            s1 += sa[j][2] + sa[j][3];
        }
        s0 += __shfl_xor_sync(0xffffffffu, s0, 1); s0 += __shfl_xor_sync(0xffffffffu, s0, 2);
        s1 += __shfl_xor_sync(0xffffffffu, s1, 1); s1 += __shfl_xor_sync(0xffffffffu, s1, 2);
        l0 = l0 * al0 + s0; l1 = l1 * al1 + s1;
        #pragma unroll
        for (int j = 0; j < 8; j++) {
            oac[j][0] *= al0; oac[j][1] *= al0; oac[j][2] *= al1; oac[j][3] *= al1;
        }
        __syncthreads();

        // V tile
        #pragma unroll
        for (int i = 0; i < 4; i++) {
            int c = tid + i * 256;
            int row = c >> 3, seg = (c & 7) * 8;
            size_t g = (size_t)(b * 512 + kt * 128 + row) * D + chd + seg;
            *(uint4*)(KVh + row * 72 + seg) = *(const uint4*)(Vh + g);
            *(uint4*)(KVl + row * 72 + seg) = *(const uint4*)(Vl + g);
        }
        __syncthreads();

        // PV: S-acc fragments repacked in-register as A-fragments
        #pragma unroll
        for (int kc2 = 0; kc2 < 8; kc2++) {
            uint32_t ah[4], alr[4];
            split_pair(sa[2*kc2][0],   sa[2*kc2][1],   ah[0], alr[0]);
            split_pair(sa[2*kc2][2],   sa[2*kc2][3],   ah[1], alr[1]);
            split_pair(sa[2*kc2+1][0], sa[2*kc2+1][1], ah[2], alr[2]);
            split_pair(sa[2*kc2+1][2], sa[2*kc2+1][3], ah[3], alr[3]);
            #pragma unroll
            for (int j2 = 0; j2 < 4; j2++) {
                int kr = kc2 * 16 + (lane & 7) + ((lane >> 3) & 1) * 8;
                int dof = j2 * 16 + (lane >> 4) * 8;
                uint32_t vh[4], vl[4];
                ldm_x4_t(vh, KVh + kr * 72 + dof);
                ldm_x4_t(vl, KVl + kr * 72 + dof);
                mma16816(oac[2*j2],   ah,  vh[0], vh[1]);
                mma16816(oac[2*j2],   ah,  vl[0], vl[1]);
                mma16816(oac[2*j2],   alr, vh[0], vh[1]);
                mma16816(oac[2*j2+1], ah,  vh[2], vh[3]);
                mma16816(oac[2*j2+1], ah,  vl[2], vl[3]);
                mma16816(oac[2*j2+1], alr, vh[2], vh[3]);
            }
        }
        __syncthreads();
    }

    float i0 = 1.f / l0, i1 = 1.f / l1;
    int row0 = rb + warp * 16 + (lane >> 2);
    #pragma unroll
    for (int j = 0; j < 8; j++) {
        int col = chd + j * 8 + (lane & 3) * 2;
        uint32_t h2, l2;
        split_pair(oac[j][0] * i0, oac[j][1] * i0, h2, l2);
        *(uint32_t*)(Ch + (size_t)row0 * D + col) = h2;
        *(uint32_t*)(Cl + (size_t)row0 * D + col) = l2;
        split_pair(oac[j][2] * i1, oac[j][3] * i1, h2, l2);
        *(uint32_t*)(Ch + (size_t)(row0 + 8) * D + col) = h2;
        *(uint32_t*)(Cl + (size_t)(row0 + 8) * D + col) = l2;
    }
}

// ---------------- residual + layernorm (emits fp32 + bf16 hi/lo) ----------------
__device__ __forceinline__ float block_sum256(float v, float* red)
{
    #pragma unroll
    for (int o = 16; o; o >>= 1) v += __shfl_xor_sync(0xffffffffu, v, o);
    int w = threadIdx.x >> 5;
    if ((threadIdx.x & 31) == 0) red[w] = v;
    __syncthreads();
    if (threadIdx.x < 8) {
        v = red[threadIdx.x];
        #pragma unroll
        for (int o = 4; o; o >>= 1) v += __shfl_xor_sync(0xffu, v, o);
        if (threadIdx.x == 0) red[0] = v;
    }
    __syncthreads();
    float r = red[0];
    __syncthreads();
    return r;
}

__global__ __launch_bounds__(256) void ln_kernel(
    const float* __restrict__ x, const float* __restrict__ o,
    const float* __restrict__ sc, const float* __restrict__ bi,
    float* __restrict__ out, bf16* __restrict__ oh, bf16* __restrict__ ol)
{
    __shared__ float red[8];
    size_t base = (size_t)blockIdx.x * 768;
    int tid = threadIdx.x;
    float v[3];
    #pragma unroll
    for (int i = 0; i < 3; i++) {
        int d = tid + i * 256;
        v[i] = x[base + d] + o[base + d];
    }
    float mu = block_sum256(v[0] + v[1] + v[2], red) * (1.0f / 768.0f);
    float d0 = v[0] - mu, d1 = v[1] - mu, d2 = v[2] - mu;
    float var = block_sum256(d0 * d0 + d1 * d1 + d2 * d2, red) * (1.0f / 768.0f);
    float rstd = rsqrtf(var + 1e-12f);
    #pragma unroll
    for (int i = 0; i < 3; i++) {
        int d = tid + i * 256;
        float r = (v[i] - mu) * rstd * sc[d] + bi[d];
        out[base + d] = r;
        bf16 hh = __float2bfloat16(r);
        oh[base + d] = hh;
        ol[base + d] = __float2bfloat16(r - __bfloat162float(hh));
    }
}

// ---------------- launch ----------------
extern "C" void kernel_launch(void* const* d_in, const int* in_sizes, int n_in,
                              void* d_out, int out_size)
{
    (void)in_sizes; (void)n_in; (void)out_size;
    const float* hs = (const float*)d_in[0];
    const float* rw = (const float*)d_in[1];
    const float* qc[6], * vc[6];
    for (int i = 0; i < 6; i++) { qc[i] = (const float*)d_in[2 + i]; vc[i] = (const float*)d_in[8 + i]; }
    const float* Wq = (const float*)d_in[14];
    const float* Wk = (const float*)d_in[15];
    const float* Wv = (const float*)d_in[16];
    const float* Wo = (const float*)d_in[17];
    const float* bq = (const float*)d_in[18];
    const float* bk = (const float*)d_in[19];
    const float* bv = (const float*)d_in[20];
    const float* bo = (const float*)d_in[21];
    const float* lns = (const float*)d_in[22];
    const float* lnb = (const float*)d_in[23];

    float *x, *o;
    bf16 *xh, *xl, *qh, *ql, *kh, *kl, *vh, *vl, *chn, *cl;
    bf16 *Wqa_h, *Wqa_l, *Wva_h, *Wva_l, *Wk_h, *Wk_l, *Wo_h, *Wo_l;
    cudaGetSymbolAddress((void**)&x, g_x);
    cudaGetSymbolAddress((void**)&o, g_o);
    cudaGetSymbolAddress((void**)&xh, g_xh); cudaGetSymbolAddress((void**)&xl, g_xl);
    cudaGetSymbolAddress((void**)&qh, g_qh); cudaGetSymbolAddress((void**)&ql, g_ql);
    cudaGetSymbolAddress((void**)&kh, g_kh); cudaGetSymbolAddress((void**)&kl, g_kl);
    cudaGetSymbolAddress((void**)&vh, g_vh); cudaGetSymbolAddress((void**)&vl, g_vl);
    cudaGetSymbolAddress((void**)&chn, g_ch); cudaGetSymbolAddress((void**)&cl, g_cl);
    cudaGetSymbolAddress((void**)&Wqa_h, g_Wqa_h); cudaGetSymbolAddress((void**)&Wqa_l, g_Wqa_l);
    cudaGetSymbolAddress((void**)&Wva_h, g_Wva_h); cudaGetSymbolAddress((void**)&Wva_l, g_Wva_l);
    cudaGetSymbolAddress((void**)&Wk_h, g_Wk_h);   cudaGetSymbolAddress((void**)&Wk_l, g_Wk_l);
    cudaGetSymbolAddress((void**)&Wo_h, g_Wo_h);   cudaGetSymbolAddress((void**)&Wo_l, g_Wo_l);

    const int GEMM_SMEM = 8 * 5120 * 2;   // 80 KB
    cudaFuncSetAttribute(gemm_mma<1>, cudaFuncAttributeMaxDynamicSharedMemorySize, GEMM_SMEM);
    cudaFuncSetAttribute(gemm_mma<0>, cudaFuncAttributeMaxDynamicSharedMemorySize, GEMM_SMEM);

    router_kernel<<<1, 768>>>(hs, rw);
    tt_lr_kernel<<<dim3(12, 2), 256>>>(qc[0], qc[1], qc[2], qc[3], qc[4], qc[5],
                                       vc[0], vc[1], vc[2], vc[3], vc[4], vc[5]);
    tt_build_kernel<<<dim3(DD / 256, 12, 2), 256>>>(Wq, Wv);
    convert_split<<<(NW + 255) / 256, 256>>>(Wk, Wk_h, Wk_l, NW);
    convert_split<<<(NW + 255) / 256, 256>>>(Wo, Wo_h, Wo_l, NW);
    convert_split<<<(M_ROWS * D + 255) / 256, 256>>>(hs, xh, xl, M_ROWS * D);

    for (int l = 0; l < 12; l++) {
        const float* xin = l ? (const float*)x : hs;
        float* xout = (l == 11) ? (float*)d_out : x;
        size_t wo = (size_t)l * DD;
        size_t bofs = (size_t)l * D;

        gemm_mma<1><<<dim3(6, 128, 3), 256, GEMM_SMEM>>>(
            xh, xl,
            Wqa_h + wo, Wqa_l + wo, Wk_h + wo, Wk_l + wo, Wva_h + wo, Wva_l + wo,
            bq + bofs, bk + bofs, bv + bofs,
            qh, ql, kh, kl, vh, vl);

        attn_mma<<<dim3(4, 12, 32), 256>>>(qh, ql, kh, kl, vh, vl, chn, cl);

        gemm_mma<0><<<dim3(6, 128, 1), 256, GEMM_SMEM>>>(
            chn, cl,
            Wo_h + wo, Wo_l + wo, Wo_h + wo, Wo_l + wo, Wo_h + wo, Wo_l + wo,
            bo + bofs, bo + bofs, bo + bofs,
            o, nullptr, o, nullptr, o, nullptr);

        ln_kernel<<<16384, 256>>>(xin, o, lns + bofs, lnb + bofs, xout, xh, xl);
    }
}

// round 4
// speedup vs baseline: 3.5529x; 1.4623x over previous
#include <cuda_runtime.h>
#include <cuda_fp16.h>
#include <cstdint>

#define D 768
#define DD (768*768)
#define M_ROWS (32*512)
#define L_LAYERS 12
#define NW (L_LAYERS*DD)

typedef __half f16;

// ---------------- scratch (device globals; no allocation allowed) ----------------
__device__ float g_x[M_ROWS*D];
__device__ float g_o[M_ROWS*D];
__device__ f16 g_xh[M_ROWS*D], g_xl[M_ROWS*D];
__device__ f16 g_qh[M_ROWS*D], g_ql[M_ROWS*D];
__device__ f16 g_kh[M_ROWS*D];
__device__ f16 g_vh[M_ROWS*D];
__device__ f16 g_ch[M_ROWS*D], g_cl[M_ROWS*D];
__device__ f16 g_Wqa_h[NW], g_Wva_h[NW], g_Wk_h[NW], g_Wo_h[NW];
__device__ float g_Lf[24*6144], g_Rf[24*6144];
__device__ int   g_expert;

// ---------------- small helpers ----------------
__device__ __forceinline__ void split_pair(float v0, float v1, uint32_t& hi, uint32_t& lo)
{
    f16 h0 = __float2half_rn(v0), h1 = __float2half_rn(v1);
    float r0 = v0 - __half2float(h0), r1 = v1 - __half2float(h1);
    __half2 H = __halves2half2(h0, h1);
    __half2 L = __floats2half2_rn(r0, r1);
    hi = *reinterpret_cast<uint32_t*>(&H);
    lo = *reinterpret_cast<uint32_t*>(&L);
}
__device__ __forceinline__ uint32_t pack_h2(float v0, float v1)
{
    __half2 H = __floats2half2_rn(v0, v1);
    return *reinterpret_cast<uint32_t*>(&H);
}

__device__ __forceinline__ void ldm_x4(uint32_t* r, const f16* p)
{
    uint32_t a = (uint32_t)__cvta_generic_to_shared(p);
    asm volatile("ldmatrix.sync.aligned.m8n8.x4.shared.b16 {%0,%1,%2,%3}, [%4];"
        : "=r"(r[0]), "=r"(r[1]), "=r"(r[2]), "=r"(r[3]) : "r"(a));
}
__device__ __forceinline__ void ldm_x4_t(uint32_t* r, const f16* p)
{
    uint32_t a = (uint32_t)__cvta_generic_to_shared(p);
    asm volatile("ldmatrix.sync.aligned.m8n8.x4.trans.shared.b16 {%0,%1,%2,%3}, [%4];"
        : "=r"(r[0]), "=r"(r[1]), "=r"(r[2]), "=r"(r[3]) : "r"(a));
}
__device__ __forceinline__ void mma16816(float* d, const uint32_t* a, uint32_t b0, uint32_t b1)
{
    asm volatile("mma.sync.aligned.m16n8k16.row.col.f32.f16.f16.f32 "
        "{%0,%1,%2,%3}, {%4,%5,%6,%7}, {%8,%9}, {%0,%1,%2,%3};"
        : "+f"(d[0]), "+f"(d[1]), "+f"(d[2]), "+f"(d[3])
        : "r"(a[0]), "r"(a[1]), "r"(a[2]), "r"(a[3]), "r"(b0), "r"(b1));
}
__device__ __forceinline__ void cp16(const f16* smem_dst, const f16* gsrc)
{
    uint32_t s = (uint32_t)__cvta_generic_to_shared(smem_dst);
    asm volatile("cp.async.cg.shared.global [%0], [%1], 16;" :: "r"(s), "l"(gsrc));
}

// ---------------- router ----------------
__global__ void router_kernel(const float* __restrict__ hs, const float* __restrict__ rw)
{
    __shared__ float pooled[768];
    __shared__ float logits[8];
    int tid = threadIdx.x;
    const float* base = hs + (size_t)31 * 512 * 768;
    float s = 0.f;
    for (int i = 0; i < 512; i++) s += base[(size_t)i * 768 + tid];
    pooled[tid] = s * (1.0f / 512.0f);
    __syncthreads();
    int w = tid >> 5, lane = tid & 31;
    if (w < 8) {
        float p = 0.f;
        for (int d = lane; d < 768; d += 32) p += pooled[d] * rw[d * 8 + w];
        #pragma unroll
        for (int o = 16; o; o >>= 1) p += __shfl_xor_sync(0xffffffffu, p, o);
        if (lane == 0) logits[w] = p;
    }
    __syncthreads();
    if (tid == 0) {
        int best = 0; float bv = logits[0];
        for (int e = 1; e < 8; e++) if (logits[e] > bv) { bv = logits[e]; best = e; }
        g_expert = best;
    }
}

// ---------------- TT factors ----------------
__global__ void tt_lr_kernel(
    const float* __restrict__ qc0, const float* __restrict__ qc1, const float* __restrict__ qc2,
    const float* __restrict__ qc3, const float* __restrict__ qc4, const float* __restrict__ qc5,
    const float* __restrict__ vc0, const float* __restrict__ vc1, const float* __restrict__ vc2,
    const float* __restrict__ vc3, const float* __restrict__ vc4, const float* __restrict__ vc5)
{
    int l = blockIdx.x, w = blockIdx.y;
    int tid = threadIdx.x;
    int e = g_expert;
    const float* c0p = (w ? vc0 : qc0) + (size_t)(e * 12 + l) * 96;
    const float* c1p = (w ? vc1 : qc1) + (size_t)(e * 12 + l) * 512;
    const float* c2p = (w ? vc2 : qc2) + (size_t)(e * 12 + l) * 512;
    const float* c3p = (w ? vc3 : qc3) + (size_t)(e * 12 + l) * 512;
    const float* c4p = (w ? vc4 : qc4) + (size_t)(e * 12 + l) * 512;
    const float* c5p = (w ? vc5 : qc5) + (size_t)(e * 12 + l) * 96;

    __shared__ float c0[96], c1[512], c2[512], c3[512], c4[512], c5[96];
    __shared__ float T2[768];
    __shared__ float U2[4096];
    for (int i = tid; i < 96; i += 256) { c0[i] = c0p[i]; c5[i] = c5p[i]; }
    for (int i = tid; i < 512; i += 256) {
        c1[i] = c1p[i]; c2[i] = c2p[i]; c3[i] = c3p[i]; c4[i] = c4p[i];
    }
    __syncthreads();

    for (int t = tid; t < 768; t += 256) {
        int j = t >> 6, l2 = (t >> 3) & 7, m = t & 7;
        float s = 0.f;
        #pragma unroll
        for (int k = 0; k < 8; k++) s += c0[j * 8 + k] * c1[((k * 8 + l2) << 3) + m];
        T2[t] = s;
    }
    for (int t = tid; t < 4096; t += 256) {
        int o = t >> 9, p = (t >> 6) & 7, r = (t >> 3) & 7, ss = t & 7;
        float s = 0.f;
        #pragma unroll
        for (int q = 0; q < 8; q++) s += c3[((o * 8 + p) << 3) + q] * c4[((q * 8 + r) << 3) + ss];
        U2[t] = s;
    }
    __syncthreads();

    int chain = w * 12 + l;
    float* lf = g_Lf + (size_t)chain * 6144;
    float* rf = g_Rf + (size_t)chain * 6144;
    for (int t = tid; t < 6144; t += 256) {
        int row = t >> 3, o = t & 7;
        int jl = row >> 3, n = row & 7;
        float s = 0.f;
        #pragma unroll
        for (int m = 0; m < 8; m++) s += T2[(jl << 3) + m] * c2[((m * 8 + n) << 3) + o];
        lf[t] = s;
    }
    for (int t = tid; t < 6144; t += 256) {
        int o = t / 768, col = t - o * 768;
        int p = col / 96; int rem = col - p * 96; int r = rem / 12; int tt = rem - r * 12;
        float s = 0.f;
        #pragma unroll
        for (int ss = 0; ss < 8; ss++) s += U2[(((o * 8 + p) << 3) + r) * 8 + ss] * c5[ss * 12 + tt];
        rf[t] = s;
    }
}

// ---------------- W_a = W + 8 * Lf·Rf, emitted as fp16 (hi only) ----------------
__global__ void tt_build_kernel(const float* __restrict__ Wq, const float* __restrict__ Wv)
{
    int l = blockIdx.y, w = blockIdx.z;
    int t = blockIdx.x * 256 + threadIdx.x;
    int row = t / 768, col = t - row * 768;
    int chain = w * 12 + l;
    const float* lf = g_Lf + (size_t)chain * 6144 + row * 8;
    const float* rf = g_Rf + (size_t)chain * 6144 + col;
    float s = 0.f;
    #pragma unroll
    for (int o = 0; o < 8; o++) s += lf[o] * rf[o * 768];
    const float* W = w ? Wv : Wq;
    float val = W[(size_t)l * DD + t] + 8.0f * s;
    f16* Wh = w ? g_Wva_h : g_Wqa_h;
    Wh[(size_t)l * DD + t] = __float2half_rn(val);
}

// ---------------- fp32 -> fp16 hi/lo split ----------------
__global__ void convert_split(const float* __restrict__ s, f16* __restrict__ h,
                              f16* __restrict__ l, int n)
{
    int i = blockIdx.x * 256 + threadIdx.x;
    if (i < n) {
        float v = s[i];
        f16 hh = __float2half_rn(v);
        h[i] = hh;
        l[i] = __float2half_rn(v - __half2float(hh));
    }
}
__global__ void convert_h(const float* __restrict__ s, f16* __restrict__ h, int n)
{
    int i = blockIdx.x * 256 + threadIdx.x;
    if (i < n) h[i] = __float2half_rn(s[i]);
}

// ---------------- GEMM: O = A @ W^T + bias, fp16-split 2-pass MMA ----------------
// tile 128x128x32, 256 threads (8 warps, 4x2), cp.async double buffered, 2 CTA/SM.
// EPI=1: write fp16 hi/lo; EPI=0: write fp32.
template<int EPI>
__global__ __launch_bounds__(256, 2) void gemm_mma(
    const f16* __restrict__ Ah, const f16* __restrict__ Al,
    const f16* __restrict__ W0h, const f16* __restrict__ W1h, const f16* __restrict__ W2h,
    const float* __restrict__ bias0, const float* __restrict__ bias1, const float* __restrict__ bias2,
    void* o0a, void* o0b, void* o1a, void* o1b, void* o2a, void* o2b)
{
    extern __shared__ f16 sm[];
    f16* sAh = sm;               // [2][128*40]
    f16* sAl = sm + 2 * 5120;
    f16* sBh = sm + 4 * 5120;

    int z = blockIdx.z;
    const f16* Wh = z == 0 ? W0h : (z == 1 ? W1h : W2h);
    const float* bias = z == 0 ? bias0 : (z == 1 ? bias1 : bias2);
    void* Oa = z == 0 ? o0a : (z == 1 ? o1a : o2a);
    void* Ob = z == 0 ? o0b : (z == 1 ? o1b : o2b);

    int tid = threadIdx.x;
    int lane = tid & 31, warp = tid >> 5;
    int wm = warp >> 1, wn = warp & 1;
    int bm = blockIdx.y * 128, bn = blockIdx.x * 128;

    float acc[2][8][4];
    #pragma unroll
    for (int i = 0; i < 2; i++)
        #pragma unroll
        for (int j = 0; j < 8; j++)
            #pragma unroll
            for (int q = 0; q < 4; q++) acc[i][j][q] = 0.f;

    #define LOAD_STAGE(KT, S)                                                     \
    {                                                                             \
        _Pragma("unroll")                                                         \
        for (int i_ = 0; i_ < 2; i_++) {                                          \
            int c_ = tid + i_ * 256;                                              \
            int row_ = c_ >> 2, seg_ = (c_ & 3) * 8;                              \
            size_t ga_ = (size_t)(bm + row_) * D + (KT) * 32 + seg_;              \
            size_t gb_ = (size_t)(bn + row_) * D + (KT) * 32 + seg_;              \
            int so_ = (S) * 5120 + row_ * 40 + seg_;                              \
            cp16(sAh + so_, Ah + ga_); cp16(sAl + so_, Al + ga_);                 \
            cp16(sBh + so_, Wh + gb_);                                            \
        }                                                                         \
        asm volatile("cp.async.commit_group;");                                   \
    }

    LOAD_STAGE(0, 0)

    for (int kt = 0; kt < 24; kt++) {
        int s = kt & 1;
        if (kt < 23) {
            LOAD_STAGE(kt + 1, s ^ 1)
            asm volatile("cp.async.wait_group 1;");
        } else {
            asm volatile("cp.async.wait_group 0;");
        }
        __syncthreads();

        #pragma unroll
        for (int kk = 0; kk < 2; kk++) {
            uint32_t afh[2][4], afl[2][4];
            #pragma unroll
            for (int im = 0; im < 2; im++) {
                int r = wm * 32 + im * 16 + (lane & 7) + ((lane >> 3) & 1) * 8;
                int ko = kk * 16 + (lane >> 4) * 8;
                ldm_x4(afh[im], sAh + s * 5120 + r * 40 + ko);
                ldm_x4(afl[im], sAl + s * 5120 + r * 40 + ko);
            }
            #pragma unroll
            for (int j2 = 0; j2 < 4; j2++) {
                int nr = wn * 64 + j2 * 16 + (lane & 7) + (lane >> 4) * 8;
                int ko = kk * 16 + ((lane >> 3) & 1) * 8;
                uint32_t bh[4];
                ldm_x4(bh, sBh + s * 5120 + nr * 40 + ko);
                #pragma unroll
                for (int im = 0; im < 2; im++) {
                    mma16816(acc[im][2*j2],   afh[im], bh[0], bh[1]);
                    mma16816(acc[im][2*j2],   afl[im], bh[0], bh[1]);
                    mma16816(acc[im][2*j2+1], afh[im], bh[2], bh[3]);
                    mma16816(acc[im][2*j2+1], afl[im], bh[2], bh[3]);
                }
            }
        }
        __syncthreads();
    }

    #pragma unroll
    for (int im = 0; im < 2; im++) {
        int row0 = bm + wm * 32 + im * 16 + (lane >> 2);
        #pragma unroll
        for (int j = 0; j < 8; j++) {
            int col = bn + wn * 64 + j * 8 + (lane & 3) * 2;
            float b0v = bias[col], b1v = bias[col + 1];
            float v00 = acc[im][j][0] + b0v, v01 = acc[im][j][1] + b1v;
            float v10 = acc[im][j][2] + b0v, v11 = acc[im][j][3] + b1v;
            if (EPI == 1) {
                uint32_t h2, l2;
                split_pair(v00, v01, h2, l2);
                *(uint32_t*)((f16*)Oa + (size_t)row0 * D + col) = h2;
                *(uint32_t*)((f16*)Ob + (size_t)row0 * D + col) = l2;
                split_pair(v10, v11, h2, l2);
                *(uint32_t*)((f16*)Oa + (size_t)(row0 + 8) * D + col) = h2;
                *(uint32_t*)((f16*)Ob + (size_t)(row0 + 8) * D + col) = l2;
            } else {
                float2 f0 = make_float2(v00, v01), f1 = make_float2(v10, v11);
                *(float2*)((float*)Oa + (size_t)row0 * D + col) = f0;
                *(float2*)((float*)Oa + (size_t)(row0 + 8) * D + col) = f1;
            }
        }
    }
}

// ---------------- GEMM for K/V: O = A @ W^T + bias, fp16 hi-only output ----------------
// (same body via EPI=2: single fp16 output)

// ---------------- flash attention, fp16-split 2-pass MMA ----------------
// grid (4 qtiles, 12 heads, 32 batch), 256 threads; warp owns 16 q-rows.
__global__ __launch_bounds__(256) void attn_mma(
    const f16* __restrict__ Qh, const f16* __restrict__ Ql,
    const f16* __restrict__ Kh, const f16* __restrict__ Vh,
    f16* __restrict__ Ch, f16* __restrict__ Cl)
{
    __shared__ f16 KVh[128 * 72], KVl[128 * 72];
    int tid = threadIdx.x, lane = tid & 31, warp = tid >> 5;
    int qt = blockIdx.x, h = blockIdx.y, b = blockIdx.z;
    int rb = b * 512 + qt * 128;
    int chd = h * 64;

    // stage Q (hi in KVh, lo in KVl)
    #pragma unroll
    for (int i = 0; i < 4; i++) {
        int c = tid + i * 256;
        int row = c >> 3, seg = (c & 7) * 8;
        *(uint4*)(KVh + row * 72 + seg) = *(const uint4*)(Qh + (size_t)(rb + row) * D + chd + seg);
        *(uint4*)(KVl + row * 72 + seg) = *(const uint4*)(Ql + (size_t)(rb + row) * D + chd + seg);
    }
    __syncthreads();
    uint32_t qfh[4][4], qfl[4][4];
    #pragma unroll
    for (int kc = 0; kc < 4; kc++) {
        int r = warp * 16 + (lane & 7) + ((lane >> 3) & 1) * 8;
        int ko = kc * 16 + (lane >> 4) * 8;
        ldm_x4(qfh[kc], KVh + r * 72 + ko);
        ldm_x4(qfl[kc], KVl + r * 72 + ko);
    }
    __syncthreads();

    float m0 = -1e30f, m1 = -1e30f, l0 = 0.f, l1 = 0.f;
    float oac[8][4];
    #pragma unroll
    for (int j = 0; j < 8; j++)
        #pragma unroll
        for (int q = 0; q < 4; q++) oac[j][q] = 0.f;

    for (int kt = 0; kt < 4; kt++) {
        // K tile (hi only) into KVh
        #pragma unroll
        for (int i = 0; i < 4; i++) {
            int c = tid + i * 256;
            int row = c >> 3, seg = (c & 7) * 8;
            size_t g = (size_t)(b * 512 + kt * 128 + row) * D + chd + seg;
            *(uint4*)(KVh + row * 72 + seg) = *(const uint4*)(Kh + g);
        }
        __syncthreads();

        float sa[16][4];
        #pragma unroll
        for (int j = 0; j < 16; j++)
            #pragma unroll
            for (int q = 0; q < 4; q++) sa[j][q] = 0.f;

        #pragma unroll
        for (int kc = 0; kc < 4; kc++) {
            #pragma unroll
            for (int j2 = 0; j2 < 8; j2++) {
                int nr = j2 * 16 + (lane & 7) + (lane >> 4) * 8;
                int ko = kc * 16 + ((lane >> 3) & 1) * 8;
                uint32_t bh[4];
                ldm_x4(bh, KVh + nr * 72 + ko);
                mma16816(sa[2*j2],   qfh[kc], bh[0], bh[1]);
                mma16816(sa[2*j2],   qfl[kc], bh[0], bh[1]);
                mma16816(sa[2*j2+1], qfh[kc], bh[2], bh[3]);
                mma16816(sa[2*j2+1], qfl[kc], bh[2], bh[3]);
            }
        }

        // online softmax (rows g = lane>>2 and g+8; stats replicated across quad)
        float mx0 = -1e30f, mx1 = -1e30f;
        #pragma unroll
        for (int j = 0; j < 16; j++) {
            sa[j][0] *= 0.125f; sa[j][1] *= 0.125f; sa[j][2] *= 0.125f; sa[j][3] *= 0.125f;
            mx0 = fmaxf(mx0, fmaxf(sa[j][0], sa[j][1]));
            mx1 = fmaxf(mx1, fmaxf(sa[j][2], sa[j][3]));
        }
        mx0 = fmaxf(mx0, __shfl_xor_sync(0xffffffffu, mx0, 1));
        mx0 = fmaxf(mx0, __shfl_xor_sync(0xffffffffu, mx0, 2));
        mx1 = fmaxf(mx1, __shfl_xor_sync(0xffffffffu, mx1, 1));
        mx1 = fmaxf(mx1, __shfl_xor_sync(0xffffffffu, mx1, 2));
        float mn0 = fmaxf(m0, mx0), mn1 = fmaxf(m1, mx1);
        float al0 = __expf(m0 - mn0), al1 = __expf(m1 - mn1);
        m0 = mn0; m1 = mn1;
        float s0 = 0.f, s1 = 0.f;
        #pragma unroll
        for (int j = 0; j < 16; j++) {
            sa[j][0] = __expf(sa[j][0] - mn0); sa[j][1] = __expf(sa[j][1] - mn0);
            sa[j][2] = __expf(sa[j][2] - mn1); sa[j][3] = __expf(sa[j][3] - mn1);
            s0 += sa[j][0] + sa[j][1];
            s1 += sa[j][2] + sa[j][3];
        }
        s0 += __shfl_xor_sync(0xffffffffu, s0, 1); s0 += __shfl_xor_sync(0xffffffffu, s0, 2);
        s1 += __shfl_xor_sync(0xffffffffu, s1, 1); s1 += __shfl_xor_sync(0xffffffffu, s1, 2);
        l0 = l0 * al0 + s0; l1 = l1 * al1 + s1;
        #pragma unroll
        for (int j = 0; j < 8; j++) {
            oac[j][0] *= al0; oac[j][1] *= al0; oac[j][2] *= al1; oac[j][3] *= al1;
        }
        __syncthreads();

        // V tile (hi only) into KVh
        #pragma unroll
        for (int i = 0; i < 4; i++) {
            int c = tid + i * 256;
            int row = c >> 3, seg = (c & 7) * 8;
            size_t g = (size_t)(b * 512 + kt * 128 + row) * D + chd + seg;
            *(uint4*)(KVh + row * 72 + seg) = *(const uint4*)(Vh + g);
        }
        __syncthreads();

        // PV: P split into hi/lo fragments in-register, V hi only
        #pragma unroll
        for (int kc2 = 0; kc2 < 8; kc2++) {
            uint32_t ah[4], alr[4];
            split_pair(sa[2*kc2][0],   sa[2*kc2][1],   ah[0], alr[0]);
            split_pair(sa[2*kc2][2],   sa[2*kc2][3],   ah[1], alr[1]);
            split_pair(sa[2*kc2+1][0], sa[2*kc2+1][1], ah[2], alr[2]);
            split_pair(sa[2*kc2+1][2], sa[2*kc2+1][3], ah[3], alr[3]);
            #pragma unroll
            for (int j2 = 0; j2 < 4; j2++) {
                int kr = kc2 * 16 + (lane & 7) + ((lane >> 3) & 1) * 8;
                int dof = j2 * 16 + (lane >> 4) * 8;
                uint32_t vh[4];
                ldm_x4_t(vh, KVh + kr * 72 + dof);
                mma16816(oac[2*j2],   ah,  vh[0], vh[1]);
                mma16816(oac[2*j2],   alr, vh[0], vh[1]);
                mma16816(oac[2*j2+1], ah,  vh[2], vh[3]);
                mma16816(oac[2*j2+1], alr, vh[2], vh[3]);
            }
        }
        __syncthreads();
    }

    float i0 = 1.f / l0, i1 = 1.f / l1;
    int row0 = rb + warp * 16 + (lane >> 2);
    #pragma unroll
    for (int j = 0; j < 8; j++) {
        int col = chd + j * 8 + (lane & 3) * 2;
        uint32_t h2, l2;
        split_pair(oac[j][0] * i0, oac[j][1] * i0, h2, l2);
        *(uint32_t*)(Ch + (size_t)row0 * D + col) = h2;
        *(uint32_t*)(Cl + (size_t)row0 * D + col) = l2;
        split_pair(oac[j][2] * i1, oac[j][3] * i1, h2, l2);
        *(uint32_t*)(Ch + (size_t)(row0 + 8) * D + col) = h2;
        *(uint32_t*)(Cl + (size_t)(row0 + 8) * D + col) = l2;
    }
}

// ---------------- residual + layernorm (emits fp32 + fp16 hi/lo) ----------------
__device__ __forceinline__ float block_sum256(float v, float* red)
{
    #pragma unroll
    for (int o = 16; o; o >>= 1) v += __shfl_xor_sync(0xffffffffu, v, o);
    int w = threadIdx.x >> 5;
    if ((threadIdx.x & 31) == 0) red[w] = v;
    __syncthreads();
    if (threadIdx.x < 8) {
        v = red[threadIdx.x];
        #pragma unroll
        for (int o = 4; o; o >>= 1) v += __shfl_xor_sync(0xffu, v, o);
        if (threadIdx.x == 0) red[0] = v;
    }
    __syncthreads();
    float r = red[0];
    __syncthreads();
    return r;
}

__global__ __launch_bounds__(256) void ln_kernel(
    const float* __restrict__ x, const float* __restrict__ o,
    const float* __restrict__ sc, const float* __restrict__ bi,
    float* __restrict__ out, f16* __restrict__ oh, f16* __restrict__ ol)
{
    __shared__ float red[8];
    size_t base = (size_t)blockIdx.x * 768;
    int tid = threadIdx.x;
    float v[3];
    #pragma unroll
    for (int i = 0; i < 3; i++) {
        int d = tid + i * 256;
        v[i] = x[base + d] + o[base + d];
    }
    float mu = block_sum256(v[0] + v[1] + v[2], red) * (1.0f / 768.0f);
    float d0 = v[0] - mu, d1 = v[1] - mu, d2 = v[2] - mu;
    float var = block_sum256(d0 * d0 + d1 * d1 + d2 * d2, red) * (1.0f / 768.0f);
    float rstd = rsqrtf(var + 1e-12f);
    #pragma unroll
    for (int i = 0; i < 3; i++) {
        int d = tid + i * 256;
        float r = (v[i] - mu) * rstd * sc[d] + bi[d];
        out[base + d] = r;
        f16 hh = __float2half_rn(r);
        oh[base + d] = hh;
        ol[base + d] = __float2half_rn(r - __half2float(hh));
    }
}

// ---------------- launch ----------------
extern "C" void kernel_launch(void* const* d_in, const int* in_sizes, int n_in,
                              void* d_out, int out_size)
{
    (void)in_sizes; (void)n_in; (void)out_size;
    const float* hs = (const float*)d_in[0];
    const float* rw = (const float*)d_in[1];
    const float* qc[6], * vc[6];
    for (int i = 0; i < 6; i++) { qc[i] = (const float*)d_in[2 + i]; vc[i] = (const float*)d_in[8 + i]; }
    const float* Wq = (const float*)d_in[14];
    const float* Wk = (const float*)d_in[15];
    const float* Wv = (const float*)d_in[16];
    const float* Wo = (const float*)d_in[17];
    const float* bq = (const float*)d_in[18];
    const float* bk = (const float*)d_in[19];
    const float* bv = (const float*)d_in[20];
    const float* bo = (const float*)d_in[21];
    const float* lns = (const float*)d_in[22];
    const float* lnb = (const float*)d_in[23];

    float *x, *o;
    f16 *xh, *xl, *qh, *ql, *kh, *vh, *chn, *cl;
    f16 *Wqa_h, *Wva_h, *Wk_h, *Wo_h;
    cudaGetSymbolAddress((void**)&x, g_x);
    cudaGetSymbolAddress((void**)&o, g_o);
    cudaGetSymbolAddress((void**)&xh, g_xh); cudaGetSymbolAddress((void**)&xl, g_xl);
    cudaGetSymbolAddress((void**)&qh, g_qh); cudaGetSymbolAddress((void**)&ql, g_ql);
    cudaGetSymbolAddress((void**)&kh, g_kh);
    cudaGetSymbolAddress((void**)&vh, g_vh);
    cudaGetSymbolAddress((void**)&chn, g_ch); cudaGetSymbolAddress((void**)&cl, g_cl);
    cudaGetSymbolAddress((void**)&Wqa_h, g_Wqa_h);
    cudaGetSymbolAddress((void**)&Wva_h, g_Wva_h);
    cudaGetSymbolAddress((void**)&Wk_h, g_Wk_h);
    cudaGetSymbolAddress((void**)&Wo_h, g_Wo_h);

    const int GEMM_SMEM = 6 * 5120 * 2;   // 60 KB
    cudaFuncSetAttribute(gemm_mma<1>, cudaFuncAttributeMaxDynamicSharedMemorySize, GEMM_SMEM);
    cudaFuncSetAttribute(gemm_mma<0>, cudaFuncAttributeMaxDynamicSharedMemorySize, GEMM_SMEM);

    router_kernel<<<1, 768>>>(hs, rw);
    tt_lr_kernel<<<dim3(12, 2), 256>>>(qc[0], qc[1], qc[2], qc[3], qc[4], qc[5],
                                       vc[0], vc[1], vc[2], vc[3], vc[4], vc[5]);
    tt_build_kernel<<<dim3(DD / 256, 12, 2), 256>>>(Wq, Wv);
    convert_h<<<(NW + 255) / 256, 256>>>(Wk, Wk_h, NW);
    convert_h<<<(NW + 255) / 256, 256>>>(Wo, Wo_h, NW);
    convert_split<<<(M_ROWS * D + 255) / 256, 256>>>(hs, xh, xl, M_ROWS * D);

    for (int l = 0; l < 12; l++) {
        const float* xin = l ? (const float*)x : hs;
        float* xout = (l == 11) ? (float*)d_out : x;
        size_t wo = (size_t)l * DD;
        size_t bofs = (size_t)l * D;

        // Q gets hi+lo (needed for QK split); K gets hi+scratch-lo; V hi+scratch-lo.
        // Use g_ch/g_cl as scratch lo sinks for K and V (overwritten later by attention output).
        gemm_mma<1><<<dim3(6, 128, 3), 256, GEMM_SMEM>>>(
            xh, xl,
            Wqa_h + wo, Wk_h + wo, Wva_h + wo,
            bq + bofs, bk + bofs, bv + bofs,
            qh, ql, kh, cl, vh, cl);

        attn_mma<<<dim3(4, 12, 32), 256>>>(qh, ql, kh, vh, chn, cl);

        gemm_mma<0><<<dim3(6, 128, 1), 256, GEMM_SMEM>>>(
            chn, cl,
            Wo_h + wo, Wo_h + wo, Wo_h + wo,
            bo + bofs, bo + bofs, bo + bofs,
            o, nullptr, o, nullptr, o, nullptr);

        ln_kernel<<<16384, 256>>>(xin, o, lns + bofs, lnb + bofs, xout, xh, xl);
    }
}

// round 5
// speedup vs baseline: 5.8708x; 1.6524x over previous
#include <cuda_runtime.h>
#include <cuda_fp16.h>
#include <cstdint>

#define D 768
#define DD (768*768)
#define M_ROWS (32*512)
#define L_LAYERS 12
#define NW (L_LAYERS*DD)

typedef __half f16;

// ---------------- scratch (device globals; no allocation allowed) ----------------
__device__ float g_x[M_ROWS*D];
__device__ float g_o[M_ROWS*D];
__device__ f16 g_xh[M_ROWS*D];
__device__ f16 g_qh[M_ROWS*D];
__device__ f16 g_kh[M_ROWS*D];
__device__ f16 g_vh[M_ROWS*D];
__device__ f16 g_ch[M_ROWS*D];
__device__ f16 g_Wqa_h[NW], g_Wva_h[NW], g_Wk_h[NW], g_Wo_h[NW];
__device__ float g_Lf[24*6144], g_Rf[24*6144];
__device__ int   g_expert;

// ---------------- small helpers ----------------
__device__ __forceinline__ uint32_t pack_h2(float v0, float v1)
{
    __half2 H = __floats2half2_rn(v0, v1);
    return *reinterpret_cast<uint32_t*>(&H);
}

__device__ __forceinline__ void ldm_x4(uint32_t* r, const f16* p)
{
    uint32_t a = (uint32_t)__cvta_generic_to_shared(p);
    asm volatile("ldmatrix.sync.aligned.m8n8.x4.shared.b16 {%0,%1,%2,%3}, [%4];"
        : "=r"(r[0]), "=r"(r[1]), "=r"(r[2]), "=r"(r[3]) : "r"(a));
}
__device__ __forceinline__ void ldm_x4_t(uint32_t* r, const f16* p)
{
    uint32_t a = (uint32_t)__cvta_generic_to_shared(p);
    asm volatile("ldmatrix.sync.aligned.m8n8.x4.trans.shared.b16 {%0,%1,%2,%3}, [%4];"
        : "=r"(r[0]), "=r"(r[1]), "=r"(r[2]), "=r"(r[3]) : "r"(a));
}
__device__ __forceinline__ void mma16816(float* d, const uint32_t* a, uint32_t b0, uint32_t b1)
{
    asm volatile("mma.sync.aligned.m16n8k16.row.col.f32.f16.f16.f32 "
        "{%0,%1,%2,%3}, {%4,%5,%6,%7}, {%8,%9}, {%0,%1,%2,%3};"
        : "+f"(d[0]), "+f"(d[1]), "+f"(d[2]), "+f"(d[3])
        : "r"(a[0]), "r"(a[1]), "r"(a[2]), "r"(a[3]), "r"(b0), "r"(b1));
}
__device__ __forceinline__ void cp16(const f16* smem_dst, const f16* gsrc)
{
    uint32_t s = (uint32_t)__cvta_generic_to_shared(smem_dst);
    asm volatile("cp.async.cg.shared.global [%0], [%1], 16;" :: "r"(s), "l"(gsrc));
}

// ---------------- router ----------------
__global__ void router_kernel(const float* __restrict__ hs, const float* __restrict__ rw)
{
    __shared__ float pooled[768];
    __shared__ float logits[8];
    int tid = threadIdx.x;
    const float* base = hs + (size_t)31 * 512 * 768;
    float s = 0.f;
    for (int i = 0; i < 512; i++) s += base[(size_t)i * 768 + tid];
    pooled[tid] = s * (1.0f / 512.0f);
    __syncthreads();
    int w = tid >> 5, lane = tid & 31;
    if (w < 8) {
        float p = 0.f;
        for (int d = lane; d < 768; d += 32) p += pooled[d] * rw[d * 8 + w];
        #pragma unroll
        for (int o = 16; o; o >>= 1) p += __shfl_xor_sync(0xffffffffu, p, o);
        if (lane == 0) logits[w] = p;
    }
    __syncthreads();
    if (tid == 0) {
        int best = 0; float bv = logits[0];
        for (int e = 1; e < 8; e++) if (logits[e] > bv) { bv = logits[e]; best = e; }
        g_expert = best;
    }
}

// ---------------- TT factors ----------------
__global__ void tt_lr_kernel(
    const float* __restrict__ qc0, const float* __restrict__ qc1, const float* __restrict__ qc2,
    const float* __restrict__ qc3, const float* __restrict__ qc4, const float* __restrict__ qc5,
    const float* __restrict__ vc0, const float* __restrict__ vc1, const float* __restrict__ vc2,
    const float* __restrict__ vc3, const float* __restrict__ vc4, const float* __restrict__ vc5)
{
    int l = blockIdx.x, w = blockIdx.y;
    int tid = threadIdx.x;
    int e = g_expert;
    const float* c0p = (w ? vc0 : qc0) + (size_t)(e * 12 + l) * 96;
    const float* c1p = (w ? vc1 : qc1) + (size_t)(e * 12 + l) * 512;
    const float* c2p = (w ? vc2 : qc2) + (size_t)(e * 12 + l) * 512;
    const float* c3p = (w ? vc3 : qc3) + (size_t)(e * 12 + l) * 512;
    const float* c4p = (w ? vc4 : qc4) + (size_t)(e * 12 + l) * 512;
    const float* c5p = (w ? vc5 : qc5) + (size_t)(e * 12 + l) * 96;

    __shared__ float c0[96], c1[512], c2[512], c3[512], c4[512], c5[96];
    __shared__ float T2[768];
    __shared__ float U2[4096];
    for (int i = tid; i < 96; i += 256) { c0[i] = c0p[i]; c5[i] = c5p[i]; }
    for (int i = tid; i < 512; i += 256) {
        c1[i] = c1p[i]; c2[i] = c2p[i]; c3[i] = c3p[i]; c4[i] = c4p[i];
    }
    __syncthreads();

    for (int t = tid; t < 768; t += 256) {
        int j = t >> 6, l2 = (t >> 3) & 7, m = t & 7;
        float s = 0.f;
        #pragma unroll
        for (int k = 0; k < 8; k++) s += c0[j * 8 + k] * c1[((k * 8 + l2) << 3) + m];
        T2[t] = s;
    }
    for (int t = tid; t < 4096; t += 256) {
        int o = t >> 9, p = (t >> 6) & 7, r = (t >> 3) & 7, ss = t & 7;
        float s = 0.f;
        #pragma unroll
        for (int q = 0; q < 8; q++) s += c3[((o * 8 + p) << 3) + q] * c4[((q * 8 + r) << 3) + ss];
        U2[t] = s;
    }
    __syncthreads();

    int chain = w * 12 + l;
    float* lf = g_Lf + (size_t)chain * 6144;
    float* rf = g_Rf + (size_t)chain * 6144;
    for (int t = tid; t < 6144; t += 256) {
        int row = t >> 3, o = t & 7;
        int jl = row >> 3, n = row & 7;
        float s = 0.f;
        #pragma unroll
        for (int m = 0; m < 8; m++) s += T2[(jl << 3) + m] * c2[((m * 8 + n) << 3) + o];
        lf[t] = s;
    }
    for (int t = tid; t < 6144; t += 256) {
        int o = t / 768, col = t - o * 768;
        int p = col / 96; int rem = col - p * 96; int r = rem / 12; int tt = rem - r * 12;
        float s = 0.f;
        #pragma unroll
        for (int ss = 0; ss < 8; ss++) s += U2[(((o * 8 + p) << 3) + r) * 8 + ss] * c5[ss * 12 + tt];
        rf[t] = s;
    }
}

// ---------------- W_a = W + 8 * Lf·Rf, emitted as fp16 ----------------
__global__ void tt_build_kernel(const float* __restrict__ Wq, const float* __restrict__ Wv)
{
    int l = blockIdx.y, w = blockIdx.z;
    int t = blockIdx.x * 256 + threadIdx.x;
    int row = t / 768, col = t - row * 768;
    int chain = w * 12 + l;
    const float* lf = g_Lf + (size_t)chain * 6144 + row * 8;
    const float* rf = g_Rf + (size_t)chain * 6144 + col;
    float s = 0.f;
    #pragma unroll
    for (int o = 0; o < 8; o++) s += lf[o] * rf[o * 768];
    const float* W = w ? Wv : Wq;
    float val = W[(size_t)l * DD + t] + 8.0f * s;
    f16* Wh = w ? g_Wva_h : g_Wqa_h;
    Wh[(size_t)l * DD + t] = __float2half_rn(val);
}

// ---------------- fp32 -> fp16 ----------------
__global__ void convert_h(const float* __restrict__ s, f16* __restrict__ h, int n)
{
    int i = blockIdx.x * 256 + threadIdx.x;
    if (i < n) h[i] = __float2half_rn(s[i]);
}

// ---------------- GEMM: O = A @ W^T + bias, fp16 1-pass MMA ----------------
// tile 128x128x32, 256 threads (8 warps, 4x2), cp.async double buffered, 2 CTA/SM.
// EPI=1: write fp16; EPI=0: write fp32.
template<int EPI>
__global__ __launch_bounds__(256, 2) void gemm_mma(
    const f16* __restrict__ Ah,
    const f16* __restrict__ W0h, const f16* __restrict__ W1h, const f16* __restrict__ W2h,
    const float* __restrict__ bias0, const float* __restrict__ bias1, const float* __restrict__ bias2,
    void* o0, void* o1, void* o2)
{
    extern __shared__ f16 sm[];
    f16* sAh = sm;               // [2][128*40]
    f16* sBh = sm + 2 * 5120;

    int z = blockIdx.z;
    const f16* Wh = z == 0 ? W0h : (z == 1 ? W1h : W2h);
    const float* bias = z == 0 ? bias0 : (z == 1 ? bias1 : bias2);
    void* O = z == 0 ? o0 : (z == 1 ? o1 : o2);

    int tid = threadIdx.x;
    int lane = tid & 31, warp = tid >> 5;
    int wm = warp >> 1, wn = warp & 1;
    int bm = blockIdx.y * 128, bn = blockIdx.x * 128;

    float acc[2][8][4];
    #pragma unroll
    for (int i = 0; i < 2; i++)
        #pragma unroll
        for (int j = 0; j < 8; j++)
            #pragma unroll
            for (int q = 0; q < 4; q++) acc[i][j][q] = 0.f;

    #define LOAD_STAGE(KT, S)                                                     \
    {                                                                             \
        _Pragma("unroll")                                                         \
        for (int i_ = 0; i_ < 2; i_++) {                                          \
            int c_ = tid + i_ * 256;                                              \
            int row_ = c_ >> 2, seg_ = (c_ & 3) * 8;                              \
            size_t ga_ = (size_t)(bm + row_) * D + (KT) * 32 + seg_;              \
            size_t gb_ = (size_t)(bn + row_) * D + (KT) * 32 + seg_;              \
            int so_ = (S) * 5120 + row_ * 40 + seg_;                              \
            cp16(sAh + so_, Ah + ga_);                                            \
            cp16(sBh + so_, Wh + gb_);                                            \
        }                                                                         \
        asm volatile("cp.async.commit_group;");                                   \
    }

    LOAD_STAGE(0, 0)

    for (int kt = 0; kt < 24; kt++) {
        int s = kt & 1;
        if (kt < 23) {
            LOAD_STAGE(kt + 1, s ^ 1)
            asm volatile("cp.async.wait_group 1;");
        } else {
            asm volatile("cp.async.wait_group 0;");
        }
        __syncthreads();

        #pragma unroll
        for (int kk = 0; kk < 2; kk++) {
            uint32_t afh[2][4];
            #pragma unroll
            for (int im = 0; im < 2; im++) {
                int r = wm * 32 + im * 16 + (lane & 7) + ((lane >> 3) & 1) * 8;
                int ko = kk * 16 + (lane >> 4) * 8;
                ldm_x4(afh[im], sAh + s * 5120 + r * 40 + ko);
            }
            #pragma unroll
            for (int j2 = 0; j2 < 4; j2++) {
                int nr = wn * 64 + j2 * 16 + (lane & 7) + (lane >> 4) * 8;
                int ko = kk * 16 + ((lane >> 3) & 1) * 8;
                uint32_t bh[4];
                ldm_x4(bh, sBh + s * 5120 + nr * 40 + ko);
                #pragma unroll
                for (int im = 0; im < 2; im++) {
                    mma16816(acc[im][2*j2],   afh[im], bh[0], bh[1]);
                    mma16816(acc[im][2*j2+1], afh[im], bh[2], bh[3]);
                }
            }
        }
        __syncthreads();
    }

    #pragma unroll
    for (int im = 0; im < 2; im++) {
        int row0 = bm + wm * 32 + im * 16 + (lane >> 2);
        #pragma unroll
        for (int j = 0; j < 8; j++) {
            int col = bn + wn * 64 + j * 8 + (lane & 3) * 2;
            float b0v = bias[col], b1v = bias[col + 1];
            float v00 = acc[im][j][0] + b0v, v01 = acc[im][j][1] + b1v;
            float v10 = acc[im][j][2] + b0v, v11 = acc[im][j][3] + b1v;
            if (EPI == 1) {
                *(uint32_t*)((f16*)O + (size_t)row0 * D + col) = pack_h2(v00, v01);
                *(uint32_t*)((f16*)O + (size_t)(row0 + 8) * D + col) = pack_h2(v10, v11);
            } else {
                *(float2*)((float*)O + (size_t)row0 * D + col) = make_float2(v00, v01);
                *(float2*)((float*)O + (size_t)(row0 + 8) * D + col) = make_float2(v10, v11);
            }
        }
    }
}

// ---------------- flash attention, fp16 1-pass MMA ----------------
// grid (4 qtiles, 12 heads, 32 batch), 256 threads; warp owns 16 q-rows.
__global__ __launch_bounds__(256) void attn_mma(
    const f16* __restrict__ Qh, const f16* __restrict__ Kh, const f16* __restrict__ Vh,
    f16* __restrict__ Ch)
{
    __shared__ f16 KV[128 * 72];
    int tid = threadIdx.x, lane = tid & 31, warp = tid >> 5;
    int qt = blockIdx.x, h = blockIdx.y, b = blockIdx.z;
    int rb = b * 512 + qt * 128;
    int chd = h * 64;

    // stage Q, grab fragments
    #pragma unroll
    for (int i = 0; i < 4; i++) {
        int c = tid + i * 256;
        int row = c >> 3, seg = (c & 7) * 8;
        *(uint4*)(KV + row * 72 + seg) = *(const uint4*)(Qh + (size_t)(rb + row) * D + chd + seg);
    }
    __syncthreads();
    uint32_t qf[4][4];
    #pragma unroll
    for (int kc = 0; kc < 4; kc++) {
        int r = warp * 16 + (lane & 7) + ((lane >> 3) & 1) * 8;
        int ko = kc * 16 + (lane >> 4) * 8;
        ldm_x4(qf[kc], KV + r * 72 + ko);
    }
    __syncthreads();

    float m0 = -1e30f, m1 = -1e30f, l0 = 0.f, l1 = 0.f;
    float oac[8][4];
    #pragma unroll
    for (int j = 0; j < 8; j++)
        #pragma unroll
        for (int q = 0; q < 4; q++) oac[j][q] = 0.f;

    for (int kt = 0; kt < 4; kt++) {
        // K tile
        #pragma unroll
        for (int i = 0; i < 4; i++) {
            int c = tid + i * 256;
            int row = c >> 3, seg = (c & 7) * 8;
            size_t g = (size_t)(b * 512 + kt * 128 + row) * D + chd + seg;
            *(uint4*)(KV + row * 72 + seg) = *(const uint4*)(Kh + g);
        }
        __syncthreads();

        float sa[16][4];
        #pragma unroll
        for (int j = 0; j < 16; j++)
            #pragma unroll
            for (int q = 0; q < 4; q++) sa[j][q] = 0.f;

        #pragma unroll
        for (int kc = 0; kc < 4; kc++) {
            #pragma unroll
            for (int j2 = 0; j2 < 8; j2++) {
                int nr = j2 * 16 + (lane & 7) + (lane >> 4) * 8;
                int ko = kc * 16 + ((lane >> 3) & 1) * 8;
                uint32_t bh[4];
                ldm_x4(bh, KV + nr * 72 + ko);
                mma16816(sa[2*j2],   qf[kc], bh[0], bh[1]);
                mma16816(sa[2*j2+1], qf[kc], bh[2], bh[3]);
            }
        }

        // online softmax (rows g = lane>>2 and g+8; stats replicated across quad)
        float mx0 = -1e30f, mx1 = -1e30f;
        #pragma unroll
        for (int j = 0; j < 16; j++) {
            sa[j][0] *= 0.125f; sa[j][1] *= 0.125f; sa[j][2] *= 0.125f; sa[j][3] *= 0.125f;
            mx0 = fmaxf(mx0, fmaxf(sa[j][0], sa[j][1]));
            mx1 = fmaxf(mx1, fmaxf(sa[j][2], sa[j][3]));
        }
        mx0 = fmaxf(mx0, __shfl_xor_sync(0xffffffffu, mx0, 1));
        mx0 = fmaxf(mx0, __shfl_xor_sync(0xffffffffu, mx0, 2));
        mx1 = fmaxf(mx1, __shfl_xor_sync(0xffffffffu, mx1, 1));
        mx1 = fmaxf(mx1, __shfl_xor_sync(0xffffffffu, mx1, 2));
        float mn0 = fmaxf(m0, mx0), mn1 = fmaxf(m1, mx1);
        float al0 = __expf(m0 - mn0), al1 = __expf(m1 - mn1);
        m0 = mn0; m1 = mn1;
        float s0 = 0.f, s1 = 0.f;
        #pragma unroll
        for (int j = 0; j < 16; j++) {
            sa[j][0] = __expf(sa[j][0] - mn0); sa[j][1] = __expf(sa[j][1] - mn0);
            sa[j][2] = __expf(sa[j][2] - mn1); sa[j][3] = __expf(sa[j][3] - mn1);
            s0 += sa[j][0] + sa[j][1];
            s1 += sa[j][2] + sa[j][3];
        }
        s0 += __shfl_xor_sync(0xffffffffu, s0, 1); s0 += __shfl_xor_sync(0xffffffffu, s0, 2);
        s1 += __shfl_xor_sync(0xffffffffu, s1, 1); s1 += __shfl_xor_sync(0xffffffffu, s1, 2);
        l0 = l0 * al0 + s0; l1 = l1 * al1 + s1;
        #pragma unroll
        for (int j = 0; j < 8; j++) {
            oac[j][0] *= al0; oac[j][1] *= al0; oac[j][2] *= al1; oac[j][3] *= al1;
        }
        __syncthreads();

        // V tile
        #pragma unroll
        for (int i = 0; i < 4; i++) {
            int c = tid + i * 256;
            int row = c >> 3, seg = (c & 7) * 8;
            size_t g = (size_t)(b * 512 + kt * 128 + row) * D + chd + seg;
            *(uint4*)(KV + row * 72 + seg) = *(const uint4*)(Vh + g);
        }
        __syncthreads();

        // PV: P packed to fp16 in-register as A-fragments
        #pragma unroll
        for (int kc2 = 0; kc2 < 8; kc2++) {
            uint32_t ah[4];
            ah[0] = pack_h2(sa[2*kc2][0],   sa[2*kc2][1]);
            ah[1] = pack_h2(sa[2*kc2][2],   sa[2*kc2][3]);
            ah[2] = pack_h2(sa[2*kc2+1][0], sa[2*kc2+1][1]);
            ah[3] = pack_h2(sa[2*kc2+1][2], sa[2*kc2+1][3]);
            #pragma unroll
            for (int j2 = 0; j2 < 4; j2++) {
                int kr = kc2 * 16 + (lane & 7) + ((lane >> 3) & 1) * 8;
                int dof = j2 * 16 + (lane >> 4) * 8;
                uint32_t vh[4];
                ldm_x4_t(vh, KV + kr * 72 + dof);
                mma16816(oac[2*j2],   ah, vh[0], vh[1]);
                mma16816(oac[2*j2+1], ah, vh[2], vh[3]);
            }
        }
        __syncthreads();
    }

    float i0 = 1.f / l0, i1 = 1.f / l1;
    int row0 = rb + warp * 16 + (lane >> 2);
    #pragma unroll
    for (int j = 0; j < 8; j++) {
        int col = chd + j * 8 + (lane & 3) * 2;
        *(uint32_t*)(Ch + (size_t)row0 * D + col) = pack_h2(oac[j][0] * i0, oac[j][1] * i0);
        *(uint32_t*)(Ch + (size_t)(row0 + 8) * D + col) = pack_h2(oac[j][2] * i1, oac[j][3] * i1);
    }
}

// ---------------- residual + layernorm (emits fp32 + fp16) ----------------
__device__ __forceinline__ float block_sum256(float v, float* red)
{
    #pragma unroll
    for (int o = 16; o; o >>= 1) v += __shfl_xor_sync(0xffffffffu, v, o);
    int w = threadIdx.x >> 5;
    if ((threadIdx.x & 31) == 0) red[w] = v;
    __syncthreads();
    if (threadIdx.x < 8) {
        v = red[threadIdx.x];
        #pragma unroll
        for (int o = 4; o; o >>= 1) v += __shfl_xor_sync(0xffu, v, o);
        if (threadIdx.x == 0) red[0] = v;
    }
    __syncthreads();
    float r = red[0];
    __syncthreads();
    return r;
}

__global__ __launch_bounds__(256) void ln_kernel(
    const float* __restrict__ x, const float* __restrict__ o,
    const float* __restrict__ sc, const float* __restrict__ bi,
    float* __restrict__ out, f16* __restrict__ oh)
{
    __shared__ float red[8];
    size_t base = (size_t)blockIdx.x * 768;
    int tid = threadIdx.x;
    float v[3];
    #pragma unroll
    for (int i = 0; i < 3; i++) {
        int d = tid + i * 256;
        v[i] = x[base + d] + o[base + d];
    }
    float mu = block_sum256(v[0] + v[1] + v[2], red) * (1.0f / 768.0f);
    float d0 = v[0] - mu, d1 = v[1] - mu, d2 = v[2] - mu;
    float var = block_sum256(d0 * d0 + d1 * d1 + d2 * d2, red) * (1.0f / 768.0f);
    float rstd = rsqrtf(var + 1e-12f);
    #pragma unroll
    for (int i = 0; i < 3; i++) {
        int d = tid + i * 256;
        float r = (v[i] - mu) * rstd * sc[d] + bi[d];
        out[base + d] = r;
        oh[base + d] = __float2half_rn(r);
    }
}

// ---------------- launch ----------------
extern "C" void kernel_launch(void* const* d_in, const int* in_sizes, int n_in,
                              void* d_out, int out_size)
{
    (void)in_sizes; (void)n_in; (void)out_size;
    const float* hs = (const float*)d_in[0];
    const float* rw = (const float*)d_in[1];
    const float* qc[6], * vc[6];
    for (int i = 0; i < 6; i++) { qc[i] = (const float*)d_in[2 + i]; vc[i] = (const float*)d_in[8 + i]; }
    const float* Wq = (const float*)d_in[14];
    const float* Wk = (const float*)d_in[15];
    const float* Wv = (const float*)d_in[16];
    const float* Wo = (const float*)d_in[17];
    const float* bq = (const float*)d_in[18];
    const float* bk = (const float*)d_in[19];
    const float* bv = (const float*)d_in[20];
    const float* bo = (const float*)d_in[21];
    const float* lns = (const float*)d_in[22];
    const float* lnb = (const float*)d_in[23];

    float *x, *o;
    f16 *xh, *qh, *kh, *vh, *chn;
    f16 *Wqa_h, *Wva_h, *Wk_h, *Wo_h;
    cudaGetSymbolAddress((void**)&x, g_x);
    cudaGetSymbolAddress((void**)&o, g_o);
    cudaGetSymbolAddress((void**)&xh, g_xh);
    cudaGetSymbolAddress((void**)&qh, g_qh);
    cudaGetSymbolAddress((void**)&kh, g_kh);
    cudaGetSymbolAddress((void**)&vh, g_vh);
    cudaGetSymbolAddress((void**)&chn, g_ch);
    cudaGetSymbolAddress((void**)&Wqa_h, g_Wqa_h);
    cudaGetSymbolAddress((void**)&Wva_h, g_Wva_h);
    cudaGetSymbolAddress((void**)&Wk_h, g_Wk_h);
    cudaGetSymbolAddress((void**)&Wo_h, g_Wo_h);

    const int GEMM_SMEM = 4 * 5120 * 2;   // 40 KB
    cudaFuncSetAttribute(gemm_mma<1>, cudaFuncAttributeMaxDynamicSharedMemorySize, GEMM_SMEM);
    cudaFuncSetAttribute(gemm_mma<0>, cudaFuncAttributeMaxDynamicSharedMemorySize, GEMM_SMEM);

    router_kernel<<<1, 768>>>(hs, rw);
    tt_lr_kernel<<<dim3(12, 2), 256>>>(qc[0], qc[1], qc[2], qc[3], qc[4], qc[5],
                                       vc[0], vc[1], vc[2], vc[3], vc[4], vc[5]);
    tt_build_kernel<<<dim3(DD / 256, 12, 2), 256>>>(Wq, Wv);
    convert_h<<<(NW + 255) / 256, 256>>>(Wk, Wk_h, NW);
    convert_h<<<(NW + 255) / 256, 256>>>(Wo, Wo_h, NW);
    convert_h<<<(M_ROWS * D + 255) / 256, 256>>>(hs, xh, M_ROWS * D);

    for (int l = 0; l < 12; l++) {
        const float* xin = l ? (const float*)x : hs;
        float* xout = (l == 11) ? (float*)d_out : x;
        size_t wo = (size_t)l * DD;
        size_t bofs = (size_t)l * D;

        gemm_mma<1><<<dim3(6, 128, 3), 256, GEMM_SMEM>>>(
            xh,
            Wqa_h + wo, Wk_h + wo, Wva_h + wo,
            bq + bofs, bk + bofs, bv + bofs,
            qh, kh, vh);

        attn_mma<<<dim3(4, 12, 32), 256>>>(qh, kh, vh, chn);

        gemm_mma<0><<<dim3(6, 128, 1), 256, GEMM_SMEM>>>(
            chn,
            Wo_h + wo, Wo_h + wo, Wo_h + wo,
            bo + bofs, bo + bofs, bo + bofs,
            o, o, o);

        ln_kernel<<<16384, 256>>>(xin, o, lns + bofs, lnb + bofs, xout, xh);
    }
}

// round 6
// speedup vs baseline: 6.2012x; 1.0563x over previous
#include <cuda_runtime.h>
#include <cuda_fp16.h>
#include <cstdint>

#define D 768
#define DD (768*768)
#define M_ROWS (32*512)
#define L_LAYERS 12
#define NW (L_LAYERS*DD)

typedef __half f16;

// ---------------- scratch (device globals; no allocation allowed) ----------------
__device__ float g_x[M_ROWS*D];
__device__ float g_o[M_ROWS*D];
__device__ f16 g_xh[M_ROWS*D];
__device__ f16 g_qh[M_ROWS*D];
__device__ f16 g_kh[M_ROWS*D];
__device__ f16 g_vh[M_ROWS*D];
__device__ f16 g_ch[M_ROWS*D];
__device__ f16 g_Wqa_h[NW], g_Wva_h[NW], g_Wk_h[NW], g_Wo_h[NW];
__device__ float g_Lf[24*6144], g_Rf[24*6144];
__device__ int   g_expert;

// ---------------- small helpers ----------------
__device__ __forceinline__ uint32_t pack_h2(float v0, float v1)
{
    __half2 H = __floats2half2_rn(v0, v1);
    return *reinterpret_cast<uint32_t*>(&H);
}

__device__ __forceinline__ void ldm_x4(uint32_t* r, const f16* p)
{
    uint32_t a = (uint32_t)__cvta_generic_to_shared(p);
    asm volatile("ldmatrix.sync.aligned.m8n8.x4.shared.b16 {%0,%1,%2,%3}, [%4];"
        : "=r"(r[0]), "=r"(r[1]), "=r"(r[2]), "=r"(r[3]) : "r"(a));
}
__device__ __forceinline__ void ldm_x4_t(uint32_t* r, const f16* p)
{
    uint32_t a = (uint32_t)__cvta_generic_to_shared(p);
    asm volatile("ldmatrix.sync.aligned.m8n8.x4.trans.shared.b16 {%0,%1,%2,%3}, [%4];"
        : "=r"(r[0]), "=r"(r[1]), "=r"(r[2]), "=r"(r[3]) : "r"(a));
}
__device__ __forceinline__ void mma16816(float* d, const uint32_t* a, uint32_t b0, uint32_t b1)
{
    asm volatile("mma.sync.aligned.m16n8k16.row.col.f32.f16.f16.f32 "
        "{%0,%1,%2,%3}, {%4,%5,%6,%7}, {%8,%9}, {%0,%1,%2,%3};"
        : "+f"(d[0]), "+f"(d[1]), "+f"(d[2]), "+f"(d[3])
        : "r"(a[0]), "r"(a[1]), "r"(a[2]), "r"(a[3]), "r"(b0), "r"(b1));
}
__device__ __forceinline__ void cp16(const f16* smem_dst, const f16* gsrc)
{
    uint32_t s = (uint32_t)__cvta_generic_to_shared(smem_dst);
    asm volatile("cp.async.cg.shared.global [%0], [%1], 16;" :: "r"(s), "l"(gsrc));
}
#define CP_COMMIT() asm volatile("cp.async.commit_group;")
#define CP_WAIT(n)  asm volatile("cp.async.wait_group %0;" :: "n"(n))

// ---------------- router ----------------
__global__ void router_kernel(const float* __restrict__ hs, const float* __restrict__ rw)
{
    __shared__ float pooled[768];
    __shared__ float logits[8];
    int tid = threadIdx.x;
    const float* base = hs + (size_t)31 * 512 * 768;
    float s = 0.f;
    for (int i = 0; i < 512; i++) s += base[(size_t)i * 768 + tid];
    pooled[tid] = s * (1.0f / 512.0f);
    __syncthreads();
    int w = tid >> 5, lane = tid & 31;
    if (w < 8) {
        float p = 0.f;
        for (int d = lane; d < 768; d += 32) p += pooled[d] * rw[d * 8 + w];
        #pragma unroll
        for (int o = 16; o; o >>= 1) p += __shfl_xor_sync(0xffffffffu, p, o);
        if (lane == 0) logits[w] = p;
    }
    __syncthreads();
    if (tid == 0) {
        int best = 0; float bv = logits[0];
        for (int e = 1; e < 8; e++) if (logits[e] > bv) { bv = logits[e]; best = e; }
        g_expert = best;
    }
}

// ---------------- TT factors ----------------
__global__ void tt_lr_kernel(
    const float* __restrict__ qc0, const float* __restrict__ qc1, const float* __restrict__ qc2,
    const float* __restrict__ qc3, const float* __restrict__ qc4, const float* __restrict__ qc5,
    const float* __restrict__ vc0, const float* __restrict__ vc1, const float* __restrict__ vc2,
    const float* __restrict__ vc3, const float* __restrict__ vc4, const float* __restrict__ vc5)
{
    int l = blockIdx.x, w = blockIdx.y;
    int tid = threadIdx.x;
    int e = g_expert;
    const float* c0p = (w ? vc0 : qc0) + (size_t)(e * 12 + l) * 96;
    const float* c1p = (w ? vc1 : qc1) + (size_t)(e * 12 + l) * 512;
    const float* c2p = (w ? vc2 : qc2) + (size_t)(e * 12 + l) * 512;
    const float* c3p = (w ? vc3 : qc3) + (size_t)(e * 12 + l) * 512;
    const float* c4p = (w ? vc4 : qc4) + (size_t)(e * 12 + l) * 512;
    const float* c5p = (w ? vc5 : qc5) + (size_t)(e * 12 + l) * 96;

    __shared__ float c0[96], c1[512], c2[512], c3[512], c4[512], c5[96];
    __shared__ float T2[768];
    __shared__ float U2[4096];
    for (int i = tid; i < 96; i += 256) { c0[i] = c0p[i]; c5[i] = c5p[i]; }
    for (int i = tid; i < 512; i += 256) {
        c1[i] = c1p[i]; c2[i] = c2p[i]; c3[i] = c3p[i]; c4[i] = c4p[i];
    }
    __syncthreads();

    for (int t = tid; t < 768; t += 256) {
        int j = t >> 6, l2 = (t >> 3) & 7, m = t & 7;
        float s = 0.f;
        #pragma unroll
        for (int k = 0; k < 8; k++) s += c0[j * 8 + k] * c1[((k * 8 + l2) << 3) + m];
        T2[t] = s;
    }
    for (int t = tid; t < 4096; t += 256) {
        int o = t >> 9, p = (t >> 6) & 7, r = (t >> 3) & 7, ss = t & 7;
        float s = 0.f;
        #pragma unroll
        for (int q = 0; q < 8; q++) s += c3[((o * 8 + p) << 3) + q] * c4[((q * 8 + r) << 3) + ss];
        U2[t] = s;
    }
    __syncthreads();

    int chain = w * 12 + l;
    float* lf = g_Lf + (size_t)chain * 6144;
    float* rf = g_Rf + (size_t)chain * 6144;
    for (int t = tid; t < 6144; t += 256) {
        int row = t >> 3, o = t & 7;
        int jl = row >> 3, n = row & 7;
        float s = 0.f;
        #pragma unroll
        for (int m = 0; m < 8; m++) s += T2[(jl << 3) + m] * c2[((m * 8 + n) << 3) + o];
        lf[t] = s;
    }
    for (int t = tid; t < 6144; t += 256) {
        int o = t / 768, col = t - o * 768;
        int p = col / 96; int rem = col - p * 96; int r = rem / 12; int tt = rem - r * 12;
        float s = 0.f;
        #pragma unroll
        for (int ss = 0; ss < 8; ss++) s += U2[(((o * 8 + p) << 3) + r) * 8 + ss] * c5[ss * 12 + tt];
        rf[t] = s;
    }
}

// ---------------- W_a = W + 8 * Lf·Rf, emitted as fp16 ----------------
__global__ void tt_build_kernel(const float* __restrict__ Wq, const float* __restrict__ Wv)
{
    int l = blockIdx.y, w = blockIdx.z;
    int t = blockIdx.x * 256 + threadIdx.x;
    int row = t / 768, col = t - row * 768;
    int chain = w * 12 + l;
    const float* lf = g_Lf + (size_t)chain * 6144 + row * 8;
    const float* rf = g_Rf + (size_t)chain * 6144 + col;
    float s = 0.f;
    #pragma unroll
    for (int o = 0; o < 8; o++) s += lf[o] * rf[o * 768];
    const float* W = w ? Wv : Wq;
    float val = W[(size_t)l * DD + t] + 8.0f * s;
    f16* Wh = w ? g_Wva_h : g_Wqa_h;
    Wh[(size_t)l * DD + t] = __float2half_rn(val);
}

// ---------------- fp32 -> fp16 ----------------
__global__ void convert_h(const float* __restrict__ s, f16* __restrict__ h, int n)
{
    int i = blockIdx.x * 256 + threadIdx.x;
    if (i < n) h[i] = __float2half_rn(s[i]);
}

// ---------------- GEMM: O = A @ W^T + bias, fp16 1-pass MMA ----------------
// tile 128x128x32, 256 threads (8 warps, 4x2), cp.async double buffered, 2 CTA/SM.
template<int EPI>
__global__ __launch_bounds__(256, 2) void gemm_mma(
    const f16* __restrict__ Ah,
    const f16* __restrict__ W0h, const f16* __restrict__ W1h, const f16* __restrict__ W2h,
    const float* __restrict__ bias0, const float* __restrict__ bias1, const float* __restrict__ bias2,
    void* o0, void* o1, void* o2)
{
    extern __shared__ f16 sm[];
    f16* sAh = sm;               // [2][128*40]
    f16* sBh = sm + 2 * 5120;

    int z = blockIdx.z;
    const f16* Wh = z == 0 ? W0h : (z == 1 ? W1h : W2h);
    const float* bias = z == 0 ? bias0 : (z == 1 ? bias1 : bias2);
    void* O = z == 0 ? o0 : (z == 1 ? o1 : o2);

    int tid = threadIdx.x;
    int lane = tid & 31, warp = tid >> 5;
    int wm = warp >> 1, wn = warp & 1;
    int bm = blockIdx.y * 128, bn = blockIdx.x * 128;

    float acc[2][8][4];
    #pragma unroll
    for (int i = 0; i < 2; i++)
        #pragma unroll
        for (int j = 0; j < 8; j++)
            #pragma unroll
            for (int q = 0; q < 4; q++) acc[i][j][q] = 0.f;

    #define LOAD_STAGE(KT, S)                                                     \
    {                                                                             \
        _Pragma("unroll")                                                         \
        for (int i_ = 0; i_ < 2; i_++) {                                          \
            int c_ = tid + i_ * 256;                                              \
            int row_ = c_ >> 2, seg_ = (c_ & 3) * 8;                              \
            size_t ga_ = (size_t)(bm + row_) * D + (KT) * 32 + seg_;              \
            size_t gb_ = (size_t)(bn + row_) * D + (KT) * 32 + seg_;              \
            int so_ = (S) * 5120 + row_ * 40 + seg_;                              \
            cp16(sAh + so_, Ah + ga_);                                            \
            cp16(sBh + so_, Wh + gb_);                                            \
        }                                                                         \
        CP_COMMIT();                                                              \
    }

    LOAD_STAGE(0, 0)

    for (int kt = 0; kt < 24; kt++) {
        int s = kt & 1;
        if (kt < 23) {
            LOAD_STAGE(kt + 1, s ^ 1)
            CP_WAIT(1);
        } else {
            CP_WAIT(0);
        }
        __syncthreads();

        #pragma unroll
        for (int kk = 0; kk < 2; kk++) {
            uint32_t afh[2][4];
            #pragma unroll
            for (int im = 0; im < 2; im++) {
                int r = wm * 32 + im * 16 + (lane & 7) + ((lane >> 3) & 1) * 8;
                int ko = kk * 16 + (lane >> 4) * 8;
                ldm_x4(afh[im], sAh + s * 5120 + r * 40 + ko);
            }
            #pragma unroll
            for (int j2 = 0; j2 < 4; j2++) {
                int nr = wn * 64 + j2 * 16 + (lane & 7) + (lane >> 4) * 8;
                int ko = kk * 16 + ((lane >> 3) & 1) * 8;
                uint32_t bh[4];
                ldm_x4(bh, sBh + s * 5120 + nr * 40 + ko);
                #pragma unroll
                for (int im = 0; im < 2; im++) {
                    mma16816(acc[im][2*j2],   afh[im], bh[0], bh[1]);
                    mma16816(acc[im][2*j2+1], afh[im], bh[2], bh[3]);
                }
            }
        }
        __syncthreads();
    }

    #pragma unroll
    for (int im = 0; im < 2; im++) {
        int row0 = bm + wm * 32 + im * 16 + (lane >> 2);
        #pragma unroll
        for (int j = 0; j < 8; j++) {
            int col = bn + wn * 64 + j * 8 + (lane & 3) * 2;
            float b0v = bias[col], b1v = bias[col + 1];
            float v00 = acc[im][j][0] + b0v, v01 = acc[im][j][1] + b1v;
            float v10 = acc[im][j][2] + b0v, v11 = acc[im][j][3] + b1v;
            if (EPI == 1) {
                *(uint32_t*)((f16*)O + (size_t)row0 * D + col) = pack_h2(v00, v01);
                *(uint32_t*)((f16*)O + (size_t)(row0 + 8) * D + col) = pack_h2(v10, v11);
            } else {
                *(float2*)((float*)O + (size_t)row0 * D + col) = make_float2(v00, v01);
                *(float2*)((float*)O + (size_t)(row0 + 8) * D + col) = make_float2(v10, v11);
            }
        }
    }
}

// ---------------- flash attention, fp16 1-pass MMA, cp.async pipelined ----------------
// grid (4 qtiles, 12 heads, 32 batch), 256 threads; warp owns 16 q-rows.
// SMEM: Q + K0/K1 + V0/V1 buffers (5 x 128x72 f16 = 90KB dynamic).
#define ATT_BUF 9216   // f16 elements per buffer (128*72)
__global__ __launch_bounds__(256) void attn_mma(
    const f16* __restrict__ Qh, const f16* __restrict__ Kh, const f16* __restrict__ Vh,
    f16* __restrict__ Ch)
{
    extern __shared__ f16 asm_[];
    f16* sQ = asm_;
    f16* sK[2] = { asm_ + ATT_BUF, asm_ + 2 * ATT_BUF };
    f16* sV[2] = { asm_ + 3 * ATT_BUF, asm_ + 4 * ATT_BUF };

    int tid = threadIdx.x, lane = tid & 31, warp = tid >> 5;
    int qt = blockIdx.x, h = blockIdx.y, b = blockIdx.z;
    int rb = b * 512 + qt * 128;
    int chd = h * 64;

    // async tile loader: 1024 16B-chunks over 256 threads
    #define ATT_PREFETCH(SRC, KT, DST)                                            \
    {                                                                             \
        _Pragma("unroll")                                                         \
        for (int i_ = 0; i_ < 4; i_++) {                                          \
            int c_ = tid + i_ * 256;                                              \
            int row_ = c_ >> 3, seg_ = (c_ & 7) * 8;                              \
            size_t g_ = (size_t)(b * 512 + (KT) * 128 + row_) * D + chd + seg_;   \
            cp16((DST) + row_ * 72 + seg_, (SRC) + g_);                           \
        }                                                                         \
        CP_COMMIT();                                                              \
    }

    // prefetch K0, V0, K1, V1  (commit order C1..C4)
    ATT_PREFETCH(Kh, 0, sK[0])
    ATT_PREFETCH(Vh, 0, sV[0])
    ATT_PREFETCH(Kh, 1, sK[1])
    ATT_PREFETCH(Vh, 1, sV[1])

    // stage Q with regular loads (separate buffer; overlaps with cp.async)
    #pragma unroll
    for (int i = 0; i < 4; i++) {
        int c = tid + i * 256;
        int row = c >> 3, seg = (c & 7) * 8;
        *(uint4*)(sQ + row * 72 + seg) = *(const uint4*)(Qh + (size_t)(rb + row) * D + chd + seg);
    }
    __syncthreads();
    uint32_t qf[4][4];
    #pragma unroll
    for (int kc = 0; kc < 4; kc++) {
        int r = warp * 16 + (lane & 7) + ((lane >> 3) & 1) * 8;
        int ko = kc * 16 + (lane >> 4) * 8;
        ldm_x4(qf[kc], sQ + r * 72 + ko);
    }

    float m0 = -1e30f, m1 = -1e30f, l0 = 0.f, l1 = 0.f;
    float oac[8][4];
    #pragma unroll
    for (int j = 0; j < 8; j++)
        #pragma unroll
        for (int q = 0; q < 4; q++) oac[j][q] = 0.f;

    #pragma unroll
    for (int kt = 0; kt < 4; kt++) {
        f16* Kb = sK[kt & 1];
        f16* Vb = sV[kt & 1];

        // wait for K_t  (commit bookkeeping: waitS = {3,3,3,1})
        if (kt < 3) { CP_WAIT(3); } else { CP_WAIT(1); }
        __syncthreads();

        float sa[16][4];
        #pragma unroll
        for (int j = 0; j < 16; j++)
            #pragma unroll
            for (int q = 0; q < 4; q++) sa[j][q] = 0.f;

        #pragma unroll
        for (int kc = 0; kc < 4; kc++) {
            #pragma unroll
            for (int j2 = 0; j2 < 8; j2++) {
                int nr = j2 * 16 + (lane & 7) + (lane >> 4) * 8;
                int ko = kc * 16 + ((lane >> 3) & 1) * 8;
                uint32_t bh[4];
                ldm_x4(bh, Kb + nr * 72 + ko);
                mma16816(sa[2*j2],   qf[kc], bh[0], bh[1]);
                mma16816(sa[2*j2+1], qf[kc], bh[2], bh[3]);
            }
        }
        __syncthreads();          // all warps done reading K buffer
        if (kt < 2) ATT_PREFETCH(Kh, kt + 2, Kb)   // overwrite K buffer

        // online softmax (rows g = lane>>2 and g+8; stats replicated across quad)
        float mx0 = -1e30f, mx1 = -1e30f;
        #pragma unroll
        for (int j = 0; j < 16; j++) {
            sa[j][0] *= 0.125f; sa[j][1] *= 0.125f; sa[j][2] *= 0.125f; sa[j][3] *= 0.125f;
            mx0 = fmaxf(mx0, fmaxf(sa[j][0], sa[j][1]));
            mx1 = fmaxf(mx1, fmaxf(sa[j][2], sa[j][3]));
        }
        mx0 = fmaxf(mx0, __shfl_xor_sync(0xffffffffu, mx0, 1));
        mx0 = fmaxf(mx0, __shfl_xor_sync(0xffffffffu, mx0, 2));
        mx1 = fmaxf(mx1, __shfl_xor_sync(0xffffffffu, mx1, 1));
        mx1 = fmaxf(mx1, __shfl_xor_sync(0xffffffffu, mx1, 2));
        float mn0 = fmaxf(m0, mx0), mn1 = fmaxf(m1, mx1);
        float al0 = __expf(m0 - mn0), al1 = __expf(m1 - mn1);
        m0 = mn0; m1 = mn1;
        float s0 = 0.f, s1 = 0.f;
        #pragma unroll
        for (int j = 0; j < 16; j++) {
            sa[j][0] = __expf(sa[j][0] - mn0); sa[j][1] = __expf(sa[j][1] - mn0);
            sa[j][2] = __expf(sa[j][2] - mn1); sa[j][3] = __expf(sa[j][3] - mn1);
            s0 += sa[j][0] + sa[j][1];
            s1 += sa[j][2] + sa[j][3];
        }
        s0 += __shfl_xor_sync(0xffffffffu, s0, 1); s0 += __shfl_xor_sync(0xffffffffu, s0, 2);
        s1 += __shfl_xor_sync(0xffffffffu, s1, 1); s1 += __shfl_xor_sync(0xffffffffu, s1, 2);
        l0 = l0 * al0 + s0; l1 = l1 * al1 + s1;
        #pragma unroll
        for (int j = 0; j < 8; j++) {
            oac[j][0] *= al0; oac[j][1] *= al0; oac[j][2] *= al1; oac[j][3] *= al1;
        }

        // wait for V_t  (waitV = {3,3,2,0})
        if (kt < 2) { CP_WAIT(3); } else if (kt == 2) { CP_WAIT(2); } else { CP_WAIT(0); }
        __syncthreads();

        // PV: P packed to fp16 in-register as A-fragments
        #pragma unroll
        for (int kc2 = 0; kc2 < 8; kc2++) {
            uint32_t ah[4];
            ah[0] = pack_h2(sa[2*kc2][0],   sa[2*kc2][1]);
            ah[1] = pack_h2(sa[2*kc2][2],   sa[2*kc2][3]);
            ah[2] = pack_h2(sa[2*kc2+1][0], sa[2*kc2+1][1]);
            ah[3] = pack_h2(sa[2*kc2+1][2], sa[2*kc2+1][3]);
            #pragma unroll
            for (int j2 = 0; j2 < 4; j2++) {
                int kr = kc2 * 16 + (lane & 7) + ((lane >> 3) & 1) * 8;
                int dof = j2 * 16 + (lane >> 4) * 8;
                uint32_t vh[4];
                ldm_x4_t(vh, Vb + kr * 72 + dof);
                mma16816(oac[2*j2],   ah, vh[0], vh[1]);
                mma16816(oac[2*j2+1], ah, vh[2], vh[3]);
            }
        }
        __syncthreads();          // all warps done reading V buffer
        if (kt < 2) ATT_PREFETCH(Vh, kt + 2, Vb)   // overwrite V buffer
    }

    float i0 = 1.f / l0, i1 = 1.f / l1;
    int row0 = rb + warp * 16 + (lane >> 2);
    #pragma unroll
    for (int j = 0; j < 8; j++) {
        int col = chd + j * 8 + (lane & 3) * 2;
        *(uint32_t*)(Ch + (size_t)row0 * D + col) = pack_h2(oac[j][0] * i0, oac[j][1] * i0);
        *(uint32_t*)(Ch + (size_t)(row0 + 8) * D + col) = pack_h2(oac[j][2] * i1, oac[j][3] * i1);
    }
}

// ---------------- residual + layernorm (emits fp32 + fp16) ----------------
__device__ __forceinline__ float block_sum256(float v, float* red)
{
    #pragma unroll
    for (int o = 16; o; o >>= 1) v += __shfl_xor_sync(0xffffffffu, v, o);
    int w = threadIdx.x >> 5;
    if ((threadIdx.x & 31) == 0) red[w] = v;
    __syncthreads();
    if (threadIdx.x < 8) {
        v = red[threadIdx.x];
        #pragma unroll
        for (int o = 4; o; o >>= 1) v += __shfl_xor_sync(0xffu, v, o);
        if (threadIdx.x == 0) red[0] = v;
    }
    __syncthreads();
    float r = red[0];
    __syncthreads();
    return r;
}

__global__ __launch_bounds__(256) void ln_kernel(
    const float* __restrict__ x, const float* __restrict__ o,
    const float* __restrict__ sc, const float* __restrict__ bi,
    float* __restrict__ out, f16* __restrict__ oh)
{
    __shared__ float red[8];
    size_t base = (size_t)blockIdx.x * 768;
    int tid = threadIdx.x;
    float v[3];
    #pragma unroll
    for (int i = 0; i < 3; i++) {
        int d = tid + i * 256;
        v[i] = x[base + d] + o[base + d];
    }
    float mu = block_sum256(v[0] + v[1] + v[2], red) * (1.0f / 768.0f);
    float d0 = v[0] - mu, d1 = v[1] - mu, d2 = v[2] - mu;
    float var = block_sum256(d0 * d0 + d1 * d1 + d2 * d2, red) * (1.0f / 768.0f);
    float rstd = rsqrtf(var + 1e-12f);
    #pragma unroll
    for (int i = 0; i < 3; i++) {
        int d = tid + i * 256;
        float r = (v[i] - mu) * rstd * sc[d] + bi[d];
        out[base + d] = r;
        oh[base + d] = __float2half_rn(r);
    }
}

// ---------------- launch ----------------
extern "C" void kernel_launch(void* const* d_in, const int* in_sizes, int n_in,
                              void* d_out, int out_size)
{
    (void)in_sizes; (void)n_in; (void)out_size;
    const float* hs = (const float*)d_in[0];
    const float* rw = (const float*)d_in[1];
    const float* qc[6], * vc[6];
    for (int i = 0; i < 6; i++) { qc[i] = (const float*)d_in[2 + i]; vc[i] = (const float*)d_in[8 + i]; }
    const float* Wq = (const float*)d_in[14];
    const float* Wk = (const float*)d_in[15];
    const float* Wv = (const float*)d_in[16];
    const float* Wo = (const float*)d_in[17];
    const float* bq = (const float*)d_in[18];
    const float* bk = (const float*)d_in[19];
    const float* bv = (const float*)d_in[20];
    const float* bo = (const float*)d_in[21];
    const float* lns = (const float*)d_in[22];
    const float* lnb = (const float*)d_in[23];

    float *x, *o;
    f16 *xh, *qh, *kh, *vh, *chn;
    f16 *Wqa_h, *Wva_h, *Wk_h, *Wo_h;
    cudaGetSymbolAddress((void**)&x, g_x);
    cudaGetSymbolAddress((void**)&o, g_o);
    cudaGetSymbolAddress((void**)&xh, g_xh);
    cudaGetSymbolAddress((void**)&qh, g_qh);
    cudaGetSymbolAddress((void**)&kh, g_kh);
    cudaGetSymbolAddress((void**)&vh, g_vh);
    cudaGetSymbolAddress((void**)&chn, g_ch);
    cudaGetSymbolAddress((void**)&Wqa_h, g_Wqa_h);
    cudaGetSymbolAddress((void**)&Wva_h, g_Wva_h);
    cudaGetSymbolAddress((void**)&Wk_h, g_Wk_h);
    cudaGetSymbolAddress((void**)&Wo_h, g_Wo_h);

    const int GEMM_SMEM = 4 * 5120 * 2;       // 40 KB
    const int ATT_SMEM = 5 * ATT_BUF * 2;     // 90 KB
    cudaFuncSetAttribute(gemm_mma<1>, cudaFuncAttributeMaxDynamicSharedMemorySize, GEMM_SMEM);
    cudaFuncSetAttribute(gemm_mma<0>, cudaFuncAttributeMaxDynamicSharedMemorySize, GEMM_SMEM);
    cudaFuncSetAttribute(attn_mma, cudaFuncAttributeMaxDynamicSharedMemorySize, ATT_SMEM);

    router_kernel<<<1, 768>>>(hs, rw);
    tt_lr_kernel<<<dim3(12, 2), 256>>>(qc[0], qc[1], qc[2], qc[3], qc[4], qc[5],
                                       vc[0], vc[1], vc[2], vc[3], vc[4], vc[5]);
    tt_build_kernel<<<dim3(DD / 256, 12, 2), 256>>>(Wq, Wv);
    convert_h<<<(NW + 255) / 256, 256>>>(Wk, Wk_h, NW);
    convert_h<<<(NW + 255) / 256, 256>>>(Wo, Wo_h, NW);
    convert_h<<<(M_ROWS * D + 255) / 256, 256>>>(hs, xh, M_ROWS * D);

    for (int l = 0; l < 12; l++) {
        const float* xin = l ? (const float*)x : hs;
        float* xout = (l == 11) ? (float*)d_out : x;
        size_t wo = (size_t)l * DD;
        size_t bofs = (size_t)l * D;

        gemm_mma<1><<<dim3(6, 128, 3), 256, GEMM_SMEM>>>(
            xh,
            Wqa_h + wo, Wk_h + wo, Wva_h + wo,
            bq + bofs, bk + bofs, bv + bofs,
            qh, kh, vh);

        attn_mma<<<dim3(4, 12, 32), 256, ATT_SMEM>>>(qh, kh, vh, chn);

        gemm_mma<0><<<dim3(6, 128, 1), 256, GEMM_SMEM>>>(
            chn,
            Wo_h + wo, Wo_h + wo, Wo_h + wo,
            bo + bofs, bo + bofs, bo + bofs,
            o, o, o);

        ln_kernel<<<16384, 256>>>(xin, o, lns + bofs, lnb + bofs, xout, xh);
    }
}

// round 7
// speedup vs baseline: 6.4730x; 1.0438x over previous
#include <cuda_runtime.h>
#include <cuda_fp16.h>
#include <cstdint>

#define D 768
#define DD (768*768)
#define M_ROWS (32*512)
#define L_LAYERS 12
#define NW (L_LAYERS*DD)

typedef __half f16;

// ---------------- scratch (device globals; no allocation allowed) ----------------
__device__ float g_x[M_ROWS*D];
__device__ f16 g_xh[M_ROWS*D];
__device__ f16 g_qh[M_ROWS*D];
__device__ f16 g_kh[M_ROWS*D];
__device__ f16 g_vh[M_ROWS*D];
__device__ f16 g_ch[M_ROWS*D];
__device__ f16 g_Wqa_h[NW], g_Wva_h[NW], g_Wk_h[NW], g_Wo_h[NW];
__device__ float g_Lf[24*6144], g_Rf[24*6144];
__device__ int   g_expert;

// ---------------- small helpers ----------------
__device__ __forceinline__ uint32_t pack_h2(float v0, float v1)
{
    __half2 H = __floats2half2_rn(v0, v1);
    return *reinterpret_cast<uint32_t*>(&H);
}

__device__ __forceinline__ void ldm_x4(uint32_t* r, const f16* p)
{
    uint32_t a = (uint32_t)__cvta_generic_to_shared(p);
    asm volatile("ldmatrix.sync.aligned.m8n8.x4.shared.b16 {%0,%1,%2,%3}, [%4];"
        : "=r"(r[0]), "=r"(r[1]), "=r"(r[2]), "=r"(r[3]) : "r"(a));
}
__device__ __forceinline__ void ldm_x4_t(uint32_t* r, const f16* p)
{
    uint32_t a = (uint32_t)__cvta_generic_to_shared(p);
    asm volatile("ldmatrix.sync.aligned.m8n8.x4.trans.shared.b16 {%0,%1,%2,%3}, [%4];"
        : "=r"(r[0]), "=r"(r[1]), "=r"(r[2]), "=r"(r[3]) : "r"(a));
}
__device__ __forceinline__ void mma16816(float* d, const uint32_t* a, uint32_t b0, uint32_t b1)
{
    asm volatile("mma.sync.aligned.m16n8k16.row.col.f32.f16.f16.f32 "
        "{%0,%1,%2,%3}, {%4,%5,%6,%7}, {%8,%9}, {%0,%1,%2,%3};"
        : "+f"(d[0]), "+f"(d[1]), "+f"(d[2]), "+f"(d[3])
        : "r"(a[0]), "r"(a[1]), "r"(a[2]), "r"(a[3]), "r"(b0), "r"(b1));
}
__device__ __forceinline__ void cp16(const f16* smem_dst, const f16* gsrc)
{
    uint32_t s = (uint32_t)__cvta_generic_to_shared(smem_dst);
    asm volatile("cp.async.cg.shared.global [%0], [%1], 16;" :: "r"(s), "l"(gsrc));
}
#define CP_COMMIT() asm volatile("cp.async.commit_group;")
#define CP_WAIT(n)  asm volatile("cp.async.wait_group %0;" :: "n"(n))

// ---------------- router ----------------
__global__ void router_kernel(const float* __restrict__ hs, const float* __restrict__ rw)
{
    __shared__ float pooled[768];
    __shared__ float logits[8];
    int tid = threadIdx.x;
    const float* base = hs + (size_t)31 * 512 * 768;
    float s = 0.f;
    for (int i = 0; i < 512; i++) s += base[(size_t)i * 768 + tid];
    pooled[tid] = s * (1.0f / 512.0f);
    __syncthreads();
    int w = tid >> 5, lane = tid & 31;
    if (w < 8) {
        float p = 0.f;
        for (int d = lane; d < 768; d += 32) p += pooled[d] * rw[d * 8 + w];
        #pragma unroll
        for (int o = 16; o; o >>= 1) p += __shfl_xor_sync(0xffffffffu, p, o);
        if (lane == 0) logits[w] = p;
    }
    __syncthreads();
    if (tid == 0) {
        int best = 0; float bv = logits[0];
        for (int e = 1; e < 8; e++) if (logits[e] > bv) { bv = logits[e]; best = e; }
        g_expert = best;
    }
}

// ---------------- TT factors ----------------
__global__ void tt_lr_kernel(
    const float* __restrict__ qc0, const float* __restrict__ qc1, const float* __restrict__ qc2,
    const float* __restrict__ qc3, const float* __restrict__ qc4, const float* __restrict__ qc5,
    const float* __restrict__ vc0, const float* __restrict__ vc1, const float* __restrict__ vc2,
    const float* __restrict__ vc3, const float* __restrict__ vc4, const float* __restrict__ vc5)
{
    int l = blockIdx.x, w = blockIdx.y;
    int tid = threadIdx.x;
    int e = g_expert;
    const float* c0p = (w ? vc0 : qc0) + (size_t)(e * 12 + l) * 96;
    const float* c1p = (w ? vc1 : qc1) + (size_t)(e * 12 + l) * 512;
    const float* c2p = (w ? vc2 : qc2) + (size_t)(e * 12 + l) * 512;
    const float* c3p = (w ? vc3 : qc3) + (size_t)(e * 12 + l) * 512;
    const float* c4p = (w ? vc4 : qc4) + (size_t)(e * 12 + l) * 512;
    const float* c5p = (w ? vc5 : qc5) + (size_t)(e * 12 + l) * 96;

    __shared__ float c0[96], c1[512], c2[512], c3[512], c4[512], c5[96];
    __shared__ float T2[768];
    __shared__ float U2[4096];
    for (int i = tid; i < 96; i += 256) { c0[i] = c0p[i]; c5[i] = c5p[i]; }
    for (int i = tid; i < 512; i += 256) {
        c1[i] = c1p[i]; c2[i] = c2p[i]; c3[i] = c3p[i]; c4[i] = c4p[i];
    }
    __syncthreads();

    for (int t = tid; t < 768; t += 256) {
        int j = t >> 6, l2 = (t >> 3) & 7, m = t & 7;
        float s = 0.f;
        #pragma unroll
        for (int k = 0; k < 8; k++) s += c0[j * 8 + k] * c1[((k * 8 + l2) << 3) + m];
        T2[t] = s;
    }
    for (int t = tid; t < 4096; t += 256) {
        int o = t >> 9, p = (t >> 6) & 7, r = (t >> 3) & 7, ss = t & 7;
        float s = 0.f;
        #pragma unroll
        for (int q = 0; q < 8; q++) s += c3[((o * 8 + p) << 3) + q] * c4[((q * 8 + r) << 3) + ss];
        U2[t] = s;
    }
    __syncthreads();

    int chain = w * 12 + l;
    float* lf = g_Lf + (size_t)chain * 6144;
    float* rf = g_Rf + (size_t)chain * 6144;
    for (int t = tid; t < 6144; t += 256) {
        int row = t >> 3, o = t & 7;
        int jl = row >> 3, n = row & 7;
        float s = 0.f;
        #pragma unroll
        for (int m = 0; m < 8; m++) s += T2[(jl << 3) + m] * c2[((m * 8 + n) << 3) + o];
        lf[t] = s;
    }
    for (int t = tid; t < 6144; t += 256) {
        int o = t / 768, col = t - o * 768;
        int p = col / 96; int rem = col - p * 96; int r = rem / 12; int tt = rem - r * 12;
        float s = 0.f;
        #pragma unroll
        for (int ss = 0; ss < 8; ss++) s += U2[(((o * 8 + p) << 3) + r) * 8 + ss] * c5[ss * 12 + tt];
        rf[t] = s;
    }
}

// ---------------- W_a = W + 8 * Lf·Rf, emitted as fp16 ----------------
__global__ void tt_build_kernel(const float* __restrict__ Wq, const float* __restrict__ Wv)
{
    int l = blockIdx.y, w = blockIdx.z;
    int t = blockIdx.x * 256 + threadIdx.x;
    int row = t / 768, col = t - row * 768;
    int chain = w * 12 + l;
    const float* lf = g_Lf + (size_t)chain * 6144 + row * 8;
    const float* rf = g_Rf + (size_t)chain * 6144 + col;
    float s = 0.f;
    #pragma unroll
    for (int o = 0; o < 8; o++) s += lf[o] * rf[o * 768];
    const float* W = w ? Wv : Wq;
    float val = W[(size_t)l * DD + t] + 8.0f * s;
    f16* Wh = w ? g_Wva_h : g_Wqa_h;
    Wh[(size_t)l * DD + t] = __float2half_rn(val);
}

// ---------------- fp32 -> fp16 ----------------
__global__ void convert_h(const float* __restrict__ s, f16* __restrict__ h, int n)
{
    int i = blockIdx.x * 256 + threadIdx.x;
    if (i < n) h[i] = __float2half_rn(s[i]);
}

// ---------------- GEMM: O = A @ W^T + bias, fp16 1-pass MMA ----------------
// tile 128x128x32, 256 threads (8 warps, 4x2), cp.async double buffered, 2 CTA/SM.
__global__ __launch_bounds__(256, 2) void gemm_mma(
    const f16* __restrict__ Ah,
    const f16* __restrict__ W0h, const f16* __restrict__ W1h, const f16* __restrict__ W2h,
    const float* __restrict__ bias0, const float* __restrict__ bias1, const float* __restrict__ bias2,
    f16* o0, f16* o1, f16* o2)
{
    extern __shared__ f16 sm[];
    f16* sAh = sm;               // [2][128*40]
    f16* sBh = sm + 2 * 5120;

    int z = blockIdx.z;
    const f16* Wh = z == 0 ? W0h : (z == 1 ? W1h : W2h);
    const float* bias = z == 0 ? bias0 : (z == 1 ? bias1 : bias2);
    f16* O = z == 0 ? o0 : (z == 1 ? o1 : o2);

    int tid = threadIdx.x;
    int lane = tid & 31, warp = tid >> 5;
    int wm = warp >> 1, wn = warp & 1;
    int bm = blockIdx.y * 128, bn = blockIdx.x * 128;

    float acc[2][8][4];
    #pragma unroll
    for (int i = 0; i < 2; i++)
        #pragma unroll
        for (int j = 0; j < 8; j++)
            #pragma unroll
            for (int q = 0; q < 4; q++) acc[i][j][q] = 0.f;

    #define LOAD_STAGE(KT, S)                                                     \
    {                                                                             \
        _Pragma("unroll")                                                         \
        for (int i_ = 0; i_ < 2; i_++) {                                          \
            int c_ = tid + i_ * 256;                                              \
            int row_ = c_ >> 2, seg_ = (c_ & 3) * 8;                              \
            size_t ga_ = (size_t)(bm + row_) * D + (KT) * 32 + seg_;              \
            size_t gb_ = (size_t)(bn + row_) * D + (KT) * 32 + seg_;              \
            int so_ = (S) * 5120 + row_ * 40 + seg_;                              \
            cp16(sAh + so_, Ah + ga_);                                            \
            cp16(sBh + so_, Wh + gb_);                                            \
        }                                                                         \
        CP_COMMIT();                                                              \
    }

    LOAD_STAGE(0, 0)

    for (int kt = 0; kt < 24; kt++) {
        int s = kt & 1;
        if (kt < 23) {
            LOAD_STAGE(kt + 1, s ^ 1)
            CP_WAIT(1);
        } else {
            CP_WAIT(0);
        }
        __syncthreads();

        #pragma unroll
        for (int kk = 0; kk < 2; kk++) {
            uint32_t afh[2][4];
            #pragma unroll
            for (int im = 0; im < 2; im++) {
                int r = wm * 32 + im * 16 + (lane & 7) + ((lane >> 3) & 1) * 8;
                int ko = kk * 16 + (lane >> 4) * 8;
                ldm_x4(afh[im], sAh + s * 5120 + r * 40 + ko);
            }
            #pragma unroll
            for (int j2 = 0; j2 < 4; j2++) {
                int nr = wn * 64 + j2 * 16 + (lane & 7) + (lane >> 4) * 8;
                int ko = kk * 16 + ((lane >> 3) & 1) * 8;
                uint32_t bh[4];
                ldm_x4(bh, sBh + s * 5120 + nr * 40 + ko);
                #pragma unroll
                for (int im = 0; im < 2; im++) {
                    mma16816(acc[im][2*j2],   afh[im], bh[0], bh[1]);
                    mma16816(acc[im][2*j2+1], afh[im], bh[2], bh[3]);
                }
            }
        }
        __syncthreads();
    }

    #pragma unroll
    for (int im = 0; im < 2; im++) {
        int row0 = bm + wm * 32 + im * 16 + (lane >> 2);
        #pragma unroll
        for (int j = 0; j < 8; j++) {
            int col = bn + wn * 64 + j * 8 + (lane & 3) * 2;
            float b0v = bias[col], b1v = bias[col + 1];
            *(uint32_t*)(O + (size_t)row0 * D + col) =
                pack_h2(acc[im][j][0] + b0v, acc[im][j][1] + b1v);
            *(uint32_t*)(O + (size_t)(row0 + 8) * D + col) =
                pack_h2(acc[im][j][2] + b0v, acc[im][j][3] + b1v);
        }
    }
}

// ---------------- flash attention, fp16 1-pass MMA, full K/V prefetch ----------------
// grid (4 qtiles, 12 heads, 32 batch), 256 threads; warp owns 16 q-rows.
// SMEM: Q + K0..K3 + V0..V3 (9 x 128x72 f16 = 162 KB), no buffer reuse.
#define ATT_BUF 9216   // f16 elements per buffer (128*72)
__global__ __launch_bounds__(256) void attn_mma(
    const f16* __restrict__ Qh, const f16* __restrict__ Kh, const f16* __restrict__ Vh,
    f16* __restrict__ Ch)
{
    extern __shared__ f16 asm_[];
    f16* sQ = asm_;

    int tid = threadIdx.x, lane = tid & 31, warp = tid >> 5;
    int qt = blockIdx.x, h = blockIdx.y, b = blockIdx.z;
    int rb = b * 512 + qt * 128;
    int chd = h * 64;

    // async tile loader: 512 16B-chunks over 256 threads
    #define ATT_PREFETCH(SRC, KT, DST)                                            \
    {                                                                             \
        _Pragma("unroll")                                                         \
        for (int i_ = 0; i_ < 4; i_++) {                                          \
            int c_ = tid + i_ * 256;                                              \
            int row_ = c_ >> 3, seg_ = (c_ & 7) * 8;                              \
            size_t g_ = (size_t)(b * 512 + (KT) * 128 + row_) * D + chd + seg_;   \
            cp16((DST) + row_ * 72 + seg_, (SRC) + g_);                           \
        }                                                                         \
        CP_COMMIT();                                                              \
    }

    // group 1: Q
    #pragma unroll
    for (int i = 0; i < 4; i++) {
        int c = tid + i * 256;
        int row = c >> 3, seg = (c & 7) * 8;
        cp16(sQ + row * 72 + seg, Qh + (size_t)(rb + row) * D + chd + seg);
    }
    CP_COMMIT();
    // groups 2..9: K0,V0,K1,V1,K2,V2,K3,V3
    #pragma unroll
    for (int t = 0; t < 4; t++) {
        ATT_PREFETCH(Kh, t, asm_ + (1 + t) * ATT_BUF)
        ATT_PREFETCH(Vh, t, asm_ + (5 + t) * ATT_BUF)
    }

    CP_WAIT(8);            // Q arrived
    __syncthreads();
    uint32_t qf[4][4];
    #pragma unroll
    for (int kc = 0; kc < 4; kc++) {
        int r = warp * 16 + (lane & 7) + ((lane >> 3) & 1) * 8;
        int ko = kc * 16 + (lane >> 4) * 8;
        ldm_x4(qf[kc], sQ + r * 72 + ko);
    }

    float m0 = -1e30f, m1 = -1e30f, l0 = 0.f, l1 = 0.f;
    float oac[8][4];
    #pragma unroll
    for (int j = 0; j < 8; j++)
        #pragma unroll
        for (int q = 0; q < 4; q++) oac[j][q] = 0.f;

    #pragma unroll
    for (int kt = 0; kt < 4; kt++) {
        f16* Kb = asm_ + (1 + kt) * ATT_BUF;
        f16* Vb = asm_ + (5 + kt) * ATT_BUF;

        // K_kt visible  (pending allowed: 7,5,3,1)
        if (kt == 0)      { CP_WAIT(7); }
        else if (kt == 1) { CP_WAIT(5); }
        else if (kt == 2) { CP_WAIT(3); }
        else              { CP_WAIT(1); }
        __syncthreads();

        float sa[16][4];
        #pragma unroll
        for (int j = 0; j < 16; j++)
            #pragma unroll
            for (int q = 0; q < 4; q++) sa[j][q] = 0.f;

        #pragma unroll
        for (int kc = 0; kc < 4; kc++) {
            #pragma unroll
            for (int j2 = 0; j2 < 8; j2++) {
                int nr = j2 * 16 + (lane & 7) + (lane >> 4) * 8;
                int ko = kc * 16 + ((lane >> 3) & 1) * 8;
                uint32_t bh[4];
                ldm_x4(bh, Kb + nr * 72 + ko);
                mma16816(sa[2*j2],   qf[kc], bh[0], bh[1]);
                mma16816(sa[2*j2+1], qf[kc], bh[2], bh[3]);
            }
        }

        // online softmax — same barrier-free region as QK, warps stagger
        float mx0 = -1e30f, mx1 = -1e30f;
        #pragma unroll
        for (int j = 0; j < 16; j++) {
            sa[j][0] *= 0.125f; sa[j][1] *= 0.125f; sa[j][2] *= 0.125f; sa[j][3] *= 0.125f;
            mx0 = fmaxf(mx0, fmaxf(sa[j][0], sa[j][1]));
            mx1 = fmaxf(mx1, fmaxf(sa[j][2], sa[j][3]));
        }
        mx0 = fmaxf(mx0, __shfl_xor_sync(0xffffffffu, mx0, 1));
        mx0 = fmaxf(mx0, __shfl_xor_sync(0xffffffffu, mx0, 2));
        mx1 = fmaxf(mx1, __shfl_xor_sync(0xffffffffu, mx1, 1));
        mx1 = fmaxf(mx1, __shfl_xor_sync(0xffffffffu, mx1, 2));
        float mn0 = fmaxf(m0, mx0), mn1 = fmaxf(m1, mx1);
        float al0 = __expf(m0 - mn0), al1 = __expf(m1 - mn1);
        m0 = mn0; m1 = mn1;
        float s0 = 0.f, s1 = 0.f;
        #pragma unroll
        for (int j = 0; j < 16; j++) {
            sa[j][0] = __expf(sa[j][0] - mn0); sa[j][1] = __expf(sa[j][1] - mn0);
            sa[j][2] = __expf(sa[j][2] - mn1); sa[j][3] = __expf(sa[j][3] - mn1);
            s0 += sa[j][0] + sa[j][1];
            s1 += sa[j][2] + sa[j][3];
        }
        s0 += __shfl_xor_sync(0xffffffffu, s0, 1); s0 += __shfl_xor_sync(0xffffffffu, s0, 2);
        s1 += __shfl_xor_sync(0xffffffffu, s1, 1); s1 += __shfl_xor_sync(0xffffffffu, s1, 2);
        l0 = l0 * al0 + s0; l1 = l1 * al1 + s1;
        #pragma unroll
        for (int j = 0; j < 8; j++) {
            oac[j][0] *= al0; oac[j][1] *= al0; oac[j][2] *= al1; oac[j][3] *= al1;
        }

        // V_kt visible  (pending allowed: 6,4,2,0)
        if (kt == 0)      { CP_WAIT(6); }
        else if (kt == 1) { CP_WAIT(4); }
        else if (kt == 2) { CP_WAIT(2); }
        else              { CP_WAIT(0); }
        __syncthreads();

        // PV: P packed to fp16 in-register as A-fragments
        #pragma unroll
        for (int kc2 = 0; kc2 < 8; kc2++) {
            uint32_t ah[4];
            ah[0] = pack_h2(sa[2*kc2][0],   sa[2*kc2][1]);
            ah[1] = pack_h2(sa[2*kc2][2],   sa[2*kc2][3]);
            ah[2] = pack_h2(sa[2*kc2+1][0], sa[2*kc2+1][1]);
            ah[3] = pack_h2(sa[2*kc2+1][2], sa[2*kc2+1][3]);
            #pragma unroll
            for (int j2 = 0; j2 < 4; j2++) {
                int kr = kc2 * 16 + (lane & 7) + ((lane >> 3) & 1) * 8;
                int dof = j2 * 16 + (lane >> 4) * 8;
                uint32_t vh[4];
                ldm_x4_t(vh, Vb + kr * 72 + dof);
                mma16816(oac[2*j2],   ah, vh[0], vh[1]);
                mma16816(oac[2*j2+1], ah, vh[2], vh[3]);
            }
        }
        // no trailing sync: buffers are never reused
    }

    float i0 = 1.f / l0, i1 = 1.f / l1;
    int row0 = rb + warp * 16 + (lane >> 2);
    #pragma unroll
    for (int j = 0; j < 8; j++) {
        int col = chd + j * 8 + (lane & 3) * 2;
        *(uint32_t*)(Ch + (size_t)row0 * D + col) = pack_h2(oac[j][0] * i0, oac[j][1] * i0);
        *(uint32_t*)(Ch + (size_t)(row0 + 8) * D + col) = pack_h2(oac[j][2] * i1, oac[j][3] * i1);
    }
}

// ---------------- residual + layernorm, warp-per-row (no block barriers) ----------------
// x fp32, o fp16; emits fp32 out + fp16 xh. 8 rows per 256-thread block.
__global__ __launch_bounds__(256) void ln_kernel(
    const float* __restrict__ x, const f16* __restrict__ o,
    const float* __restrict__ sc, const float* __restrict__ bi,
    float* __restrict__ out, f16* __restrict__ oh)
{
    int lane = threadIdx.x & 31, warp = threadIdx.x >> 5;
    size_t row = (size_t)blockIdx.x * 8 + warp;
    const float4* xp = (const float4*)(x + row * 768);
    const uint2*  op = (const uint2*)(o + row * 768);

    float v[24];
    float sum = 0.f;
    #pragma unroll
    for (int j = 0; j < 6; j++) {
        int idx = lane + 32 * j;
        float4 xv = xp[idx];
        uint2 ov = op[idx];
        __half2 o01 = *reinterpret_cast<__half2*>(&ov.x);
        __half2 o23 = *reinterpret_cast<__half2*>(&ov.y);
        float2 f01 = __half22float2(o01), f23 = __half22float2(o23);
        v[4*j+0] = xv.x + f01.x; v[4*j+1] = xv.y + f01.y;
        v[4*j+2] = xv.z + f23.x; v[4*j+3] = xv.w + f23.y;
        sum += v[4*j+0] + v[4*j+1] + v[4*j+2] + v[4*j+3];
    }
    #pragma unroll
    for (int s = 16; s; s >>= 1) sum += __shfl_xor_sync(0xffffffffu, sum, s);
    float mu = sum * (1.0f / 768.0f);
    float var = 0.f;
    #pragma unroll
    for (int i = 0; i < 24; i++) { float d = v[i] - mu; var += d * d; }
    #pragma unroll
    for (int s = 16; s; s >>= 1) var += __shfl_xor_sync(0xffffffffu, var, s);
    float rstd = rsqrtf(var * (1.0f / 768.0f) + 1e-12f);

    float4* outp = (float4*)(out + row * 768);
    uint2*  ohp  = (uint2*)(oh + row * 768);
    const float4* scp = (const float4*)sc;
    const float4* bip = (const float4*)bi;
    #pragma unroll
    for (int j = 0; j < 6; j++) {
        int idx = lane + 32 * j;
        float4 s4 = scp[idx], b4 = bip[idx];
        float4 r;
        r.x = (v[4*j+0] - mu) * rstd * s4.x + b4.x;
        r.y = (v[4*j+1] - mu) * rstd * s4.y + b4.y;
        r.z = (v[4*j+2] - mu) * rstd * s4.z + b4.z;
        r.w = (v[4*j+3] - mu) * rstd * s4.w + b4.w;
        outp[idx] = r;
        uint2 h;
        h.x = pack_h2(r.x, r.y);
        h.y = pack_h2(r.z, r.w);
        ohp[idx] = h;
    }
}

// ---------------- launch ----------------
extern "C" void kernel_launch(void* const* d_in, const int* in_sizes, int n_in,
                              void* d_out, int out_size)
{
    (void)in_sizes; (void)n_in; (void)out_size;
    const float* hs = (const float*)d_in[0];
    const float* rw = (const float*)d_in[1];
    const float* qc[6], * vc[6];
    for (int i = 0; i < 6; i++) { qc[i] = (const float*)d_in[2 + i]; vc[i] = (const float*)d_in[8 + i]; }
    const float* Wq = (const float*)d_in[14];
    const float* Wk = (const float*)d_in[15];
    const float* Wv = (const float*)d_in[16];
    const float* Wo = (const float*)d_in[17];
    const float* bq = (const float*)d_in[18];
    const float* bk = (const float*)d_in[19];
    const float* bv = (const float*)d_in[20];
    const float* bo = (const float*)d_in[21];
    const float* lns = (const float*)d_in[22];
    const float* lnb = (const float*)d_in[23];

    float *x;
    f16 *xh, *qh, *kh, *vh, *chn;
    f16 *Wqa_h, *Wva_h, *Wk_h, *Wo_h;
    cudaGetSymbolAddress((void**)&x, g_x);
    cudaGetSymbolAddress((void**)&xh, g_xh);
    cudaGetSymbolAddress((void**)&qh, g_qh);
    cudaGetSymbolAddress((void**)&kh, g_kh);
    cudaGetSymbolAddress((void**)&vh, g_vh);
    cudaGetSymbolAddress((void**)&chn, g_ch);
    cudaGetSymbolAddress((void**)&Wqa_h, g_Wqa_h);
    cudaGetSymbolAddress((void**)&Wva_h, g_Wva_h);
    cudaGetSymbolAddress((void**)&Wk_h, g_Wk_h);
    cudaGetSymbolAddress((void**)&Wo_h, g_Wo_h);

    const int GEMM_SMEM = 4 * 5120 * 2;       // 40 KB
    const int ATT_SMEM = 9 * ATT_BUF * 2;     // 162 KB
    cudaFuncSetAttribute(gemm_mma, cudaFuncAttributeMaxDynamicSharedMemorySize, GEMM_SMEM);
    cudaFuncSetAttribute(attn_mma, cudaFuncAttributeMaxDynamicSharedMemorySize, ATT_SMEM);

    router_kernel<<<1, 768>>>(hs, rw);
    tt_lr_kernel<<<dim3(12, 2), 256>>>(qc[0], qc[1], qc[2], qc[3], qc[4], qc[5],
                                       vc[0], vc[1], vc[2], vc[3], vc[4], vc[5]);
    tt_build_kernel<<<dim3(DD / 256, 12, 2), 256>>>(Wq, Wv);
    convert_h<<<(NW + 255) / 256, 256>>>(Wk, Wk_h, NW);
    convert_h<<<(NW + 255) / 256, 256>>>(Wo, Wo_h, NW);
    convert_h<<<(M_ROWS * D + 255) / 256, 256>>>(hs, xh, M_ROWS * D);

    for (int l = 0; l < 12; l++) {
        const float* xin = l ? (const float*)x : hs;
        float* xout = (l == 11) ? (float*)d_out : x;
        size_t wo = (size_t)l * DD;
        size_t bofs = (size_t)l * D;

        gemm_mma<<<dim3(6, 128, 3), 256, GEMM_SMEM>>>(
            xh,
            Wqa_h + wo, Wk_h + wo, Wva_h + wo,
            bq + bofs, bk + bofs, bv + bofs,
            qh, kh, vh);

        attn_mma<<<dim3(4, 12, 32), 256, ATT_SMEM>>>(qh, kh, vh, chn);

        // O-projection: fp16 output into qh (free after attention)
        gemm_mma<<<dim3(6, 128, 1), 256, GEMM_SMEM>>>(
            chn,
            Wo_h + wo, Wo_h + wo, Wo_h + wo,
            bo + bofs, bo + bofs, bo + bofs,
            qh, qh, qh);

        ln_kernel<<<2048, 256>>>(xin, qh, lns + bofs, lnb + bofs, xout, xh);
    }
}

// round 8
// speedup vs baseline: 6.9048x; 1.0667x over previous
#include <cuda_runtime.h>
#include <cuda_fp16.h>
#include <cstdint>

#define D 768
#define DD (768*768)
#define M_ROWS (32*512)
#define L_LAYERS 12
#define NW (L_LAYERS*DD)

typedef __half f16;

// ---------------- scratch (device globals; no allocation allowed) ----------------
__device__ f16 g_xh[M_ROWS*D];
__device__ f16 g_qh[M_ROWS*D];
__device__ f16 g_kh[M_ROWS*D];
__device__ f16 g_vh[M_ROWS*D];
__device__ f16 g_ch[M_ROWS*D];
__device__ f16 g_Wqa_h[NW], g_Wva_h[NW], g_Wk_h[NW], g_Wo_h[NW];
__device__ float g_Lf[24*6144], g_Rf[24*6144];
__device__ int   g_expert;

// ---------------- small helpers ----------------
__device__ __forceinline__ uint32_t pack_h2(float v0, float v1)
{
    __half2 H = __floats2half2_rn(v0, v1);
    return *reinterpret_cast<uint32_t*>(&H);
}

__device__ __forceinline__ void ldm_x4(uint32_t* r, const f16* p)
{
    uint32_t a = (uint32_t)__cvta_generic_to_shared(p);
    asm volatile("ldmatrix.sync.aligned.m8n8.x4.shared.b16 {%0,%1,%2,%3}, [%4];"
        : "=r"(r[0]), "=r"(r[1]), "=r"(r[2]), "=r"(r[3]) : "r"(a));
}
__device__ __forceinline__ void ldm_x4_t(uint32_t* r, const f16* p)
{
    uint32_t a = (uint32_t)__cvta_generic_to_shared(p);
    asm volatile("ldmatrix.sync.aligned.m8n8.x4.trans.shared.b16 {%0,%1,%2,%3}, [%4];"
        : "=r"(r[0]), "=r"(r[1]), "=r"(r[2]), "=r"(r[3]) : "r"(a));
}
__device__ __forceinline__ void mma16816(float* d, const uint32_t* a, uint32_t b0, uint32_t b1)
{
    asm volatile("mma.sync.aligned.m16n8k16.row.col.f32.f16.f16.f32 "
        "{%0,%1,%2,%3}, {%4,%5,%6,%7}, {%8,%9}, {%0,%1,%2,%3};"
        : "+f"(d[0]), "+f"(d[1]), "+f"(d[2]), "+f"(d[3])
        : "r"(a[0]), "r"(a[1]), "r"(a[2]), "r"(a[3]), "r"(b0), "r"(b1));
}
__device__ __forceinline__ void cp16(const f16* smem_dst, const f16* gsrc)
{
    uint32_t s = (uint32_t)__cvta_generic_to_shared(smem_dst);
    asm volatile("cp.async.cg.shared.global [%0], [%1], 16;" :: "r"(s), "l"(gsrc));
}
#define CP_COMMIT() asm volatile("cp.async.commit_group;")
#define CP_WAIT(n)  asm volatile("cp.async.wait_group %0;" :: "n"(n))

// ---------------- router ----------------
__global__ void router_kernel(const float* __restrict__ hs, const float* __restrict__ rw)
{
    __shared__ float pooled[768];
    __shared__ float logits[8];
    int tid = threadIdx.x;
    const float* base = hs + (size_t)31 * 512 * 768;
    float s = 0.f;
    for (int i = 0; i < 512; i++) s += base[(size_t)i * 768 + tid];
    pooled[tid] = s * (1.0f / 512.0f);
    __syncthreads();
    int w = tid >> 5, lane = tid & 31;
    if (w < 8) {
        float p = 0.f;
        for (int d = lane; d < 768; d += 32) p += pooled[d] * rw[d * 8 + w];
        #pragma unroll
        for (int o = 16; o; o >>= 1) p += __shfl_xor_sync(0xffffffffu, p, o);
        if (lane == 0) logits[w] = p;
    }
    __syncthreads();
    if (tid == 0) {
        int best = 0; float bv = logits[0];
        for (int e = 1; e < 8; e++) if (logits[e] > bv) { bv = logits[e]; best = e; }
        g_expert = best;
    }
}

// ---------------- TT factors ----------------
__global__ void tt_lr_kernel(
    const float* __restrict__ qc0, const float* __restrict__ qc1, const float* __restrict__ qc2,
    const float* __restrict__ qc3, const float* __restrict__ qc4, const float* __restrict__ qc5,
    const float* __restrict__ vc0, const float* __restrict__ vc1, const float* __restrict__ vc2,
    const float* __restrict__ vc3, const float* __restrict__ vc4, const float* __restrict__ vc5)
{
    int l = blockIdx.x, w = blockIdx.y;
    int tid = threadIdx.x;
    int e = g_expert;
    const float* c0p = (w ? vc0 : qc0) + (size_t)(e * 12 + l) * 96;
    const float* c1p = (w ? vc1 : qc1) + (size_t)(e * 12 + l) * 512;
    const float* c2p = (w ? vc2 : qc2) + (size_t)(e * 12 + l) * 512;
    const float* c3p = (w ? vc3 : qc3) + (size_t)(e * 12 + l) * 512;
    const float* c4p = (w ? vc4 : qc4) + (size_t)(e * 12 + l) * 512;
    const float* c5p = (w ? vc5 : qc5) + (size_t)(e * 12 + l) * 96;

    __shared__ float c0[96], c1[512], c2[512], c3[512], c4[512], c5[96];
    __shared__ float T2[768];
    __shared__ float U2[4096];
    for (int i = tid; i < 96; i += 256) { c0[i] = c0p[i]; c5[i] = c5p[i]; }
    for (int i = tid; i < 512; i += 256) {
        c1[i] = c1p[i]; c2[i] = c2p[i]; c3[i] = c3p[i]; c4[i] = c4p[i];
    }
    __syncthreads();

    for (int t = tid; t < 768; t += 256) {
        int j = t >> 6, l2 = (t >> 3) & 7, m = t & 7;
        float s = 0.f;
        #pragma unroll
        for (int k = 0; k < 8; k++) s += c0[j * 8 + k] * c1[((k * 8 + l2) << 3) + m];
        T2[t] = s;
    }
    for (int t = tid; t < 4096; t += 256) {
        int o = t >> 9, p = (t >> 6) & 7, r = (t >> 3) & 7, ss = t & 7;
        float s = 0.f;
        #pragma unroll
        for (int q = 0; q < 8; q++) s += c3[((o * 8 + p) << 3) + q] * c4[((q * 8 + r) << 3) + ss];
        U2[t] = s;
    }
    __syncthreads();

    int chain = w * 12 + l;
    float* lf = g_Lf + (size_t)chain * 6144;
    float* rf = g_Rf + (size_t)chain * 6144;
    for (int t = tid; t < 6144; t += 256) {
        int row = t >> 3, o = t & 7;
        int jl = row >> 3, n = row & 7;
        float s = 0.f;
        #pragma unroll
        for (int m = 0; m < 8; m++) s += T2[(jl << 3) + m] * c2[((m * 8 + n) << 3) + o];
        lf[t] = s;
    }
    for (int t = tid; t < 6144; t += 256) {
        int o = t / 768, col = t - o * 768;
        int p = col / 96; int rem = col - p * 96; int r = rem / 12; int tt = rem - r * 12;
        float s = 0.f;
        #pragma unroll
        for (int ss = 0; ss < 8; ss++) s += U2[(((o * 8 + p) << 3) + r) * 8 + ss] * c5[ss * 12 + tt];
        rf[t] = s;
    }
}

// ---------------- W_a = W + 8 * Lf·Rf, emitted as fp16 ----------------
__global__ void tt_build_kernel(const float* __restrict__ Wq, const float* __restrict__ Wv)
{
    int l = blockIdx.y, w = blockIdx.z;
    int t = blockIdx.x * 256 + threadIdx.x;
    int row = t / 768, col = t - row * 768;
    int chain = w * 12 + l;
    const float* lf = g_Lf + (size_t)chain * 6144 + row * 8;
    const float* rf = g_Rf + (size_t)chain * 6144 + col;
    float s = 0.f;
    #pragma unroll
    for (int o = 0; o < 8; o++) s += lf[o] * rf[o * 768];
    const float* W = w ? Wv : Wq;
    float val = W[(size_t)l * DD + t] + 8.0f * s;
    f16* Wh = w ? g_Wva_h : g_Wqa_h;
    Wh[(size_t)l * DD + t] = __float2half_rn(val);
}

// ---------------- fp32 -> fp16, 8 elements/thread ----------------
__global__ void convert_h8(const float* __restrict__ s, f16* __restrict__ h, int n8)
{
    int i = blockIdx.x * 256 + threadIdx.x;
    if (i < n8) {
        const float4* sp = (const float4*)s + (size_t)i * 2;
        float4 a = sp[0], b = sp[1];
        uint4 r;
        r.x = pack_h2(a.x, a.y); r.y = pack_h2(a.z, a.w);
        r.z = pack_h2(b.x, b.y); r.w = pack_h2(b.z, b.w);
        ((uint4*)h)[i] = r;
    }
}

// ---------------- GEMM: O = A @ W^T + bias, fp16 1-pass MMA ----------------
// tile 128x128x32, 256 threads (8 warps, 4x2), 3-stage cp.async, 1 sync/stage, 2 CTA/SM.
// scale0 applied to z==0 output (folds attention 1/sqrt(hd) into Q).
__global__ __launch_bounds__(256, 2) void gemm_mma(
    const f16* __restrict__ Ah,
    const f16* __restrict__ W0h, const f16* __restrict__ W1h, const f16* __restrict__ W2h,
    const float* __restrict__ bias0, const float* __restrict__ bias1, const float* __restrict__ bias2,
    f16* o0, f16* o1, f16* o2, float scale0)
{
    extern __shared__ f16 sm[];
    f16* sAh = sm;               // [3][128*40]
    f16* sBh = sm + 3 * 5120;

    int z = blockIdx.z;
    const f16* Wh = z == 0 ? W0h : (z == 1 ? W1h : W2h);
    const float* bias = z == 0 ? bias0 : (z == 1 ? bias1 : bias2);
    f16* O = z == 0 ? o0 : (z == 1 ? o1 : o2);
    float scl = z == 0 ? scale0 : 1.0f;

    int tid = threadIdx.x;
    int lane = tid & 31, warp = tid >> 5;
    int wm = warp >> 1, wn = warp & 1;
    int bm = blockIdx.y * 128, bn = blockIdx.x * 128;

    float acc[2][8][4];
    #pragma unroll
    for (int i = 0; i < 2; i++)
        #pragma unroll
        for (int j = 0; j < 8; j++)
            #pragma unroll
            for (int q = 0; q < 4; q++) acc[i][j][q] = 0.f;

    #define LOAD_STAGE(KT, S)                                                     \
    {                                                                             \
        _Pragma("unroll")                                                         \
        for (int i_ = 0; i_ < 2; i_++) {                                          \
            int c_ = tid + i_ * 256;                                              \
            int row_ = c_ >> 2, seg_ = (c_ & 3) * 8;                              \
            size_t ga_ = (size_t)(bm + row_) * D + (KT) * 32 + seg_;              \
            size_t gb_ = (size_t)(bn + row_) * D + (KT) * 32 + seg_;              \
            int so_ = (S) * 5120 + row_ * 40 + seg_;                              \
            cp16(sAh + so_, Ah + ga_);                                            \
            cp16(sBh + so_, Wh + gb_);                                            \
        }                                                                         \
        CP_COMMIT();                                                              \
    }

    LOAD_STAGE(0, 0)
    LOAD_STAGE(1, 1)

    int s = 0, sl = 2;   // compute buffer, next load buffer
    for (int kt = 0; kt < 24; kt++) {
        if (kt < 23) { CP_WAIT(1); } else { CP_WAIT(0); }
        __syncthreads();
        if (kt < 22) {
            LOAD_STAGE(kt + 2, sl)
            sl = (sl == 2) ? 0 : sl + 1;
        }

        #pragma unroll
        for (int kk = 0; kk < 2; kk++) {
            uint32_t afh[2][4];
            #pragma unroll
            for (int im = 0; im < 2; im++) {
                int r = wm * 32 + im * 16 + (lane & 7) + ((lane >> 3) & 1) * 8;
                int ko = kk * 16 + (lane >> 4) * 8;
                ldm_x4(afh[im], sAh + s * 5120 + r * 40 + ko);
            }
            #pragma unroll
            for (int j2 = 0; j2 < 4; j2++) {
                int nr = wn * 64 + j2 * 16 + (lane & 7) + (lane >> 4) * 8;
                int ko = kk * 16 + ((lane >> 3) & 1) * 8;
                uint32_t bh[4];
                ldm_x4(bh, sBh + s * 5120 + nr * 40 + ko);
                #pragma unroll
                for (int im = 0; im < 2; im++) {
                    mma16816(acc[im][2*j2],   afh[im], bh[0], bh[1]);
                    mma16816(acc[im][2*j2+1], afh[im], bh[2], bh[3]);
                }
            }
        }
        s = (s == 2) ? 0 : s + 1;
    }

    #pragma unroll
    for (int im = 0; im < 2; im++) {
        int row0 = bm + wm * 32 + im * 16 + (lane >> 2);
        #pragma unroll
        for (int j = 0; j < 8; j++) {
            int col = bn + wn * 64 + j * 8 + (lane & 3) * 2;
            float b0v = bias[col], b1v = bias[col + 1];
            *(uint32_t*)(O + (size_t)row0 * D + col) =
                pack_h2((acc[im][j][0] + b0v) * scl, (acc[im][j][1] + b1v) * scl);
            *(uint32_t*)(O + (size_t)(row0 + 8) * D + col) =
                pack_h2((acc[im][j][2] + b0v) * scl, (acc[im][j][3] + b1v) * scl);
        }
    }
}

// ---------------- flash attention, fp16 1-pass MMA, full K/V prefetch ----------------
// grid (4 qtiles, 12 heads, 32 batch), 256 threads; warp owns 16 q-rows.
// SMEM: Q + K0..K3 + V0..V3 (9 x 128x72 f16 = 162 KB), no buffer reuse.
// Q comes pre-scaled by 1/8 from the projection GEMM.
#define ATT_BUF 9216   // f16 elements per buffer (128*72)
__global__ __launch_bounds__(256) void attn_mma(
    const f16* __restrict__ Qh, const f16* __restrict__ Kh, const f16* __restrict__ Vh,
    f16* __restrict__ Ch)
{
    extern __shared__ f16 asm_[];
    f16* sQ = asm_;

    int tid = threadIdx.x, lane = tid & 31, warp = tid >> 5;
    int qt = blockIdx.x, h = blockIdx.y, b = blockIdx.z;
    int rb = b * 512 + qt * 128;
    int chd = h * 64;

    #define ATT_PREFETCH(SRC, KT, DST)                                            \
    {                                                                             \
        _Pragma("unroll")                                                         \
        for (int i_ = 0; i_ < 4; i_++) {                                          \
            int c_ = tid + i_ * 256;                                              \
            int row_ = c_ >> 3, seg_ = (c_ & 7) * 8;                              \
            size_t g_ = (size_t)(b * 512 + (KT) * 128 + row_) * D + chd + seg_;   \
            cp16((DST) + row_ * 72 + seg_, (SRC) + g_);                           \
        }                                                                         \
        CP_COMMIT();                                                              \
    }

    // group 1: Q
    #pragma unroll
    for (int i = 0; i < 4; i++) {
        int c = tid + i * 256;
        int row = c >> 3, seg = (c & 7) * 8;
        cp16(sQ + row * 72 + seg, Qh + (size_t)(rb + row) * D + chd + seg);
    }
    CP_COMMIT();
    // groups 2..9: K0,V0,K1,V1,K2,V2,K3,V3
    #pragma unroll
    for (int t = 0; t < 4; t++) {
        ATT_PREFETCH(Kh, t, asm_ + (1 + t) * ATT_BUF)
        ATT_PREFETCH(Vh, t, asm_ + (5 + t) * ATT_BUF)
    }

    CP_WAIT(8);            // Q arrived
    __syncthreads();
    uint32_t qf[4][4];
    #pragma unroll
    for (int kc = 0; kc < 4; kc++) {
        int r = warp * 16 + (lane & 7) + ((lane >> 3) & 1) * 8;
        int ko = kc * 16 + (lane >> 4) * 8;
        ldm_x4(qf[kc], sQ + r * 72 + ko);
    }

    float m0 = -1e30f, m1 = -1e30f, l0 = 0.f, l1 = 0.f;
    float oac[8][4];
    #pragma unroll
    for (int j = 0; j < 8; j++)
        #pragma unroll
        for (int q = 0; q < 4; q++) oac[j][q] = 0.f;

    #pragma unroll
    for (int kt = 0; kt < 4; kt++) {
        f16* Kb = asm_ + (1 + kt) * ATT_BUF;
        f16* Vb = asm_ + (5 + kt) * ATT_BUF;

        // K_kt visible  (pending allowed: 7,5,3,1)
        if (kt == 0)      { CP_WAIT(7); }
        else if (kt == 1) { CP_WAIT(5); }
        else if (kt == 2) { CP_WAIT(3); }
        else              { CP_WAIT(1); }
        __syncthreads();

        float sa[16][4];
        #pragma unroll
        for (int j = 0; j < 16; j++)
            #pragma unroll
            for (int q = 0; q < 4; q++) sa[j][q] = 0.f;

        #pragma unroll
        for (int kc = 0; kc < 4; kc++) {
            #pragma unroll
            for (int j2 = 0; j2 < 8; j2++) {
                int nr = j2 * 16 + (lane & 7) + (lane >> 4) * 8;
                int ko = kc * 16 + ((lane >> 3) & 1) * 8;
                uint32_t bh[4];
                ldm_x4(bh, Kb + nr * 72 + ko);
                mma16816(sa[2*j2],   qf[kc], bh[0], bh[1]);
                mma16816(sa[2*j2+1], qf[kc], bh[2], bh[3]);
            }
        }

        // online softmax — Q pre-scaled, so sa already holds scores/8
        float mx0 = -1e30f, mx1 = -1e30f;
        #pragma unroll
        for (int j = 0; j < 16; j++) {
            mx0 = fmaxf(mx0, fmaxf(sa[j][0], sa[j][1]));
            mx1 = fmaxf(mx1, fmaxf(sa[j][2], sa[j][3]));
        }
        mx0 = fmaxf(mx0, __shfl_xor_sync(0xffffffffu, mx0, 1));
        mx0 = fmaxf(mx0, __shfl_xor_sync(0xffffffffu, mx0, 2));
        mx1 = fmaxf(mx1, __shfl_xor_sync(0xffffffffu, mx1, 1));
        mx1 = fmaxf(mx1, __shfl_xor_sync(0xffffffffu, mx1, 2));
        float mn0 = fmaxf(m0, mx0), mn1 = fmaxf(m1, mx1);
        float al0 = __expf(m0 - mn0), al1 = __expf(m1 - mn1);
        m0 = mn0; m1 = mn1;
        float s0 = 0.f, s1 = 0.f;
        #pragma unroll
        for (int j = 0; j < 16; j++) {
            sa[j][0] = __expf(sa[j][0] - mn0); sa[j][1] = __expf(sa[j][1] - mn0);
            sa[j][2] = __expf(sa[j][2] - mn1); sa[j][3] = __expf(sa[j][3] - mn1);
            s0 += sa[j][0] + sa[j][1];
            s1 += sa[j][2] + sa[j][3];
        }
        s0 += __shfl_xor_sync(0xffffffffu, s0, 1); s0 += __shfl_xor_sync(0xffffffffu, s0, 2);
        s1 += __shfl_xor_sync(0xffffffffu, s1, 1); s1 += __shfl_xor_sync(0xffffffffu, s1, 2);
        l0 = l0 * al0 + s0; l1 = l1 * al1 + s1;
        #pragma unroll
        for (int j = 0; j < 8; j++) {
            oac[j][0] *= al0; oac[j][1] *= al0; oac[j][2] *= al1; oac[j][3] *= al1;
        }

        // V_kt visible  (pending allowed: 6,4,2,0)
        if (kt == 0)      { CP_WAIT(6); }
        else if (kt == 1) { CP_WAIT(4); }
        else if (kt == 2) { CP_WAIT(2); }
        else              { CP_WAIT(0); }
        __syncthreads();

        // PV: P packed to fp16 in-register as A-fragments
        #pragma unroll
        for (int kc2 = 0; kc2 < 8; kc2++) {
            uint32_t ah[4];
            ah[0] = pack_h2(sa[2*kc2][0],   sa[2*kc2][1]);
            ah[1] = pack_h2(sa[2*kc2][2],   sa[2*kc2][3]);
            ah[2] = pack_h2(sa[2*kc2+1][0], sa[2*kc2+1][1]);
            ah[3] = pack_h2(sa[2*kc2+1][2], sa[2*kc2+1][3]);
            #pragma unroll
            for (int j2 = 0; j2 < 4; j2++) {
                int kr = kc2 * 16 + (lane & 7) + ((lane >> 3) & 1) * 8;
                int dof = j2 * 16 + (lane >> 4) * 8;
                uint32_t vh[4];
                ldm_x4_t(vh, Vb + kr * 72 + dof);
                mma16816(oac[2*j2],   ah, vh[0], vh[1]);
                mma16816(oac[2*j2+1], ah, vh[2], vh[3]);
            }
        }
        // no trailing sync: buffers are never reused
    }

    float i0 = 1.f / l0, i1 = 1.f / l1;
    int row0 = rb + warp * 16 + (lane >> 2);
    #pragma unroll
    for (int j = 0; j < 8; j++) {
        int col = chd + j * 8 + (lane & 3) * 2;
        *(uint32_t*)(Ch + (size_t)row0 * D + col) = pack_h2(oac[j][0] * i0, oac[j][1] * i0);
        *(uint32_t*)(Ch + (size_t)(row0 + 8) * D + col) = pack_h2(oac[j][2] * i1, oac[j][3] * i1);
    }
}

// ---------------- residual + layernorm, warp-per-row, fp16 residual stream ----------------
// FIRST: residual input from fp32 x32; else from fp16 x16.
// LAST: write fp32 out32 (d_out); else write fp16 oh.
template<int FIRST, int LAST>
__global__ __launch_bounds__(256) void ln_kernel(
    const float* __restrict__ x32, const f16* __restrict__ x16,
    const f16* __restrict__ o,
    const float* __restrict__ sc, const float* __restrict__ bi,
    float* __restrict__ out32, f16* __restrict__ oh)
{
    int lane = threadIdx.x & 31, warp = threadIdx.x >> 5;
    size_t row = (size_t)blockIdx.x * 8 + warp;
    const uint2* op = (const uint2*)(o + row * 768);

    float v[24];
    float sum = 0.f;
    #pragma unroll
    for (int j = 0; j < 6; j++) {
        int idx = lane + 32 * j;
        float xv0, xv1, xv2, xv3;
        if (FIRST) {
            float4 xv = ((const float4*)(x32 + row * 768))[idx];
            xv0 = xv.x; xv1 = xv.y; xv2 = xv.z; xv3 = xv.w;
        } else {
            uint2 xv = ((const uint2*)(x16 + row * 768))[idx];
            float2 a = __half22float2(*reinterpret_cast<__half2*>(&xv.x));
            float2 b = __half22float2(*reinterpret_cast<__half2*>(&xv.y));
            xv0 = a.x; xv1 = a.y; xv2 = b.x; xv3 = b.y;
        }
        uint2 ov = op[idx];
        float2 f01 = __half22float2(*reinterpret_cast<__half2*>(&ov.x));
        float2 f23 = __half22float2(*reinterpret_cast<__half2*>(&ov.y));
        v[4*j+0] = xv0 + f01.x; v[4*j+1] = xv1 + f01.y;
        v[4*j+2] = xv2 + f23.x; v[4*j+3] = xv3 + f23.y;
        sum += v[4*j+0] + v[4*j+1] + v[4*j+2] + v[4*j+3];
    }
    #pragma unroll
    for (int s = 16; s; s >>= 1) sum += __shfl_xor_sync(0xffffffffu, sum, s);
    float mu = sum * (1.0f / 768.0f);
    float var = 0.f;
    #pragma unroll
    for (int i = 0; i < 24; i++) { float d = v[i] - mu; var += d * d; }
    #pragma unroll
    for (int s = 16; s; s >>= 1) var += __shfl_xor_sync(0xffffffffu, var, s);
    float rstd = rsqrtf(var * (1.0f / 768.0f) + 1e-12f);

    const float4* scp = (const float4*)sc;
    const float4* bip = (const float4*)bi;
    #pragma unroll
    for (int j = 0; j < 6; j++) {
        int idx = lane + 32 * j;
        float4 s4 = scp[idx], b4 = bip[idx];
        float4 r;
        r.x = (v[4*j+0] - mu) * rstd * s4.x + b4.x;
        r.y = (v[4*j+1] - mu) * rstd * s4.y + b4.y;
        r.z = (v[4*j+2] - mu) * rstd * s4.z + b4.z;
        r.w = (v[4*j+3] - mu) * rstd * s4.w + b4.w;
        if (LAST) {
            ((float4*)(out32 + row * 768))[idx] = r;
        } else {
            uint2 h;
            h.x = pack_h2(r.x, r.y);
            h.y = pack_h2(r.z, r.w);
            ((uint2*)(oh + row * 768))[idx] = h;
        }
    }
}

// ---------------- launch ----------------
extern "C" void kernel_launch(void* const* d_in, const int* in_sizes, int n_in,
                              void* d_out, int out_size)
{
    (void)in_sizes; (void)n_in; (void)out_size;
    const float* hs = (const float*)d_in[0];
    const float* rw = (const float*)d_in[1];
    const float* qc[6], * vc[6];
    for (int i = 0; i < 6; i++) { qc[i] = (const float*)d_in[2 + i]; vc[i] = (const float*)d_in[8 + i]; }
    const float* Wq = (const float*)d_in[14];
    const float* Wk = (const float*)d_in[15];
    const float* Wv = (const float*)d_in[16];
    const float* Wo = (const float*)d_in[17];
    const float* bq = (const float*)d_in[18];
    const float* bk = (const float*)d_in[19];
    const float* bv = (const float*)d_in[20];
    const float* bo = (const float*)d_in[21];
    const float* lns = (const float*)d_in[22];
    const float* lnb = (const float*)d_in[23];

    f16 *xh, *qh, *kh, *vh, *chn;
    f16 *Wqa_h, *Wva_h, *Wk_h, *Wo_h;
    cudaGetSymbolAddress((void**)&xh, g_xh);
    cudaGetSymbolAddress((void**)&qh, g_qh);
    cudaGetSymbolAddress((void**)&kh, g_kh);
    cudaGetSymbolAddress((void**)&vh, g_vh);
    cudaGetSymbolAddress((void**)&chn, g_ch);
    cudaGetSymbolAddress((void**)&Wqa_h, g_Wqa_h);
    cudaGetSymbolAddress((void**)&Wva_h, g_Wva_h);
    cudaGetSymbolAddress((void**)&Wk_h, g_Wk_h);
    cudaGetSymbolAddress((void**)&Wo_h, g_Wo_h);

    const int GEMM_SMEM = 6 * 5120 * 2;       // 60 KB (3 stages)
    const int ATT_SMEM = 9 * ATT_BUF * 2;     // 162 KB
    cudaFuncSetAttribute(gemm_mma, cudaFuncAttributeMaxDynamicSharedMemorySize, GEMM_SMEM);
    cudaFuncSetAttribute(attn_mma, cudaFuncAttributeMaxDynamicSharedMemorySize, ATT_SMEM);

    router_kernel<<<1, 768>>>(hs, rw);
    tt_lr_kernel<<<dim3(12, 2), 256>>>(qc[0], qc[1], qc[2], qc[3], qc[4], qc[5],
                                       vc[0], vc[1], vc[2], vc[3], vc[4], vc[5]);
    tt_build_kernel<<<dim3(DD / 256, 12, 2), 256>>>(Wq, Wv);
    convert_h8<<<(NW / 8 + 255) / 256, 256>>>(Wk, Wk_h, NW / 8);
    convert_h8<<<(NW / 8 + 255) / 256, 256>>>(Wo, Wo_h, NW / 8);
    convert_h8<<<(M_ROWS * D / 8 + 255) / 256, 256>>>(hs, xh, M_ROWS * D / 8);

    for (int l = 0; l < 12; l++) {
        size_t wo = (size_t)l * DD;
        size_t bofs = (size_t)l * D;

        gemm_mma<<<dim3(6, 128, 3), 256, GEMM_SMEM>>>(
            xh,
            Wqa_h + wo, Wk_h + wo, Wva_h + wo,
            bq + bofs, bk + bofs, bv + bofs,
            qh, kh, vh, 0.125f);

        attn_mma<<<dim3(4, 12, 32), 256, ATT_SMEM>>>(qh, kh, vh, chn);

        // O-projection: fp16 output into qh (free after attention)
        gemm_mma<<<dim3(6, 128, 1), 256, GEMM_SMEM>>>(
            chn,
            Wo_h + wo, Wo_h + wo, Wo_h + wo,
            bo + bofs, bo + bofs, bo + bofs,
            qh, qh, qh, 1.0f);

        if (l == 0) {
            ln_kernel<1, 0><<<2048, 256>>>(hs, nullptr, qh,
                lns + bofs, lnb + bofs, nullptr, xh);
        } else if (l < 11) {
            ln_kernel<0, 0><<<2048, 256>>>(nullptr, xh, qh,
                lns + bofs, lnb + bofs, nullptr, xh);
        } else {
            ln_kernel<0, 1><<<2048, 256>>>(nullptr, xh, qh,
                lns + bofs, lnb + bofs, (float*)d_out, nullptr);
        }
    }
}